// round 2
// baseline (speedup 1.0000x reference)
#include <cuda_runtime.h>
#include <cuda_bf16.h>
#include <cstdint>

// ---------------- problem constants ----------------
#define S_IMG 1024
#define S_TXT 512
#define S_TOT 1536
#define NH    24
#define HD    128
#define HID   3072
#define IPD   2048
#define LIP   16
#define EPS_F 1e-6f
#define SM_SCALE 0.08838834764831845f  // 1/sqrt(128)

// ---------------- scratch (static device memory; no allocation) ----------------
__device__ float g_q [S_IMG * HID];
__device__ float g_k [S_IMG * HID];
__device__ float g_v [S_IMG * HID];
__device__ float g_eq[S_TXT * HID];
__device__ float g_ek[S_TXT * HID];
__device__ float g_ev[S_TXT * HID];
__device__ float g_ipk[LIP * HID];
__device__ float g_ipv[LIP * HID];
__device__ float g_qf[(size_t)NH * S_TOT * HD];
__device__ float g_kf[(size_t)NH * S_TOT * HD];
__device__ float g_vf[(size_t)NH * S_TOT * HD];
__device__ float g_ctx[(size_t)S_TOT * HID];

// ---------------- packed f32x2 helpers ----------------
typedef unsigned long long u64;

__device__ __forceinline__ u64 pack2(float x) {
    u64 r; asm("mov.b64 %0, {%1, %2};" : "=l"(r) : "f"(x), "f"(x)); return r;
}
__device__ __forceinline__ u64 fma2(u64 a, u64 b, u64 c) {
    u64 r; asm("fma.rn.f32x2 %0, %1, %2, %3;" : "=l"(r) : "l"(a), "l"(b), "l"(c)); return r;
}
__device__ __forceinline__ float2 unpack2(u64 v) {
    float2 f; asm("mov.b64 {%0, %1}, %2;" : "=f"(f.x), "=f"(f.y) : "l"(v)); return f;
}

// ---------------- SGEMM: C[M,N] = A[M,K] @ W[K,N] + bias[N] ----------------
// 128x128 tile, BK=8, 256 threads, 8x8 per thread, packed f32x2 inner product.
__global__ __launch_bounds__(256) void sgemm_bias(
    const float* __restrict__ A, const float* __restrict__ W,
    const float* __restrict__ bias, float* __restrict__ C,
    int M, int K, int N)
{
    __shared__ float As[8][128];   // transposed A tile: As[k][m]
    __shared__ float Bs[8][128];   // Bs[k][n]

    const int t  = threadIdx.x;
    const int tx = t & 15, ty = t >> 4;
    const int bn = blockIdx.x * 128, bm = blockIdx.y * 128;

    const int aRow = bm + (t >> 1);
    const int aK0  = (t & 1) * 4;
    const int bK   = t >> 5;          // 0..7
    const int bC   = (t & 31) * 4;

    const bool aValid = aRow < M;
    const float* Ap = A + (size_t)aRow * K + aK0;
    const float* Wp = W + (size_t)bK * N + bn + bC;

    u64 acc[8][4];
#pragma unroll
    for (int m = 0; m < 8; m++)
#pragma unroll
        for (int p = 0; p < 4; p++) acc[m][p] = 0ull;

    for (int kt = 0; kt < K; kt += 8) {
        float4 av = make_float4(0.f, 0.f, 0.f, 0.f);
        if (aValid) av = *(const float4*)(Ap + kt);
        float4 bv = *(const float4*)(Wp + (size_t)kt * N);

        As[aK0 + 0][t >> 1] = av.x;
        As[aK0 + 1][t >> 1] = av.y;
        As[aK0 + 2][t >> 1] = av.z;
        As[aK0 + 3][t >> 1] = av.w;
        *(float4*)&Bs[bK][bC] = bv;
        __syncthreads();

#pragma unroll
        for (int kk = 0; kk < 8; kk++) {
            float4 a0 = *(const float4*)&As[kk][ty * 8];
            float4 a1 = *(const float4*)&As[kk][ty * 8 + 4];
            u64 am[8];
            am[0] = pack2(a0.x); am[1] = pack2(a0.y);
            am[2] = pack2(a0.z); am[3] = pack2(a0.w);
            am[4] = pack2(a1.x); am[5] = pack2(a1.y);
            am[6] = pack2(a1.z); am[7] = pack2(a1.w);
            const u64* bp = (const u64*)&Bs[kk][tx * 8];
            u64 b0 = bp[0], b1 = bp[1], b2 = bp[2], b3 = bp[3];
#pragma unroll
            for (int m = 0; m < 8; m++) {
                acc[m][0] = fma2(am[m], b0, acc[m][0]);
                acc[m][1] = fma2(am[m], b1, acc[m][1]);
                acc[m][2] = fma2(am[m], b2, acc[m][2]);
                acc[m][3] = fma2(am[m], b3, acc[m][3]);
            }
        }
        __syncthreads();
    }

    const int cCol = bn + tx * 8;
    float bb[8];
#pragma unroll
    for (int i = 0; i < 8; i++) bb[i] = bias[cCol + i];

#pragma unroll
    for (int m = 0; m < 8; m++) {
        int row = bm + ty * 8 + m;
        if (row < M) {
            float* cp = C + (size_t)row * N + cCol;
#pragma unroll
            for (int p = 0; p < 4; p++) {
                float2 v = unpack2(acc[m][p]);
                cp[2 * p]     = v.x + bb[2 * p];
                cp[2 * p + 1] = v.y + bb[2 * p + 1];
            }
        }
    }
}

// ---------------- prepare: rms-norm + rope on q/k, copy v, into [H][S][D] ----------------
__global__ __launch_bounds__(128) void prepare_qkv(
    const float* __restrict__ q,  const float* __restrict__ k,  const float* __restrict__ v,
    const float* __restrict__ eq, const float* __restrict__ ek, const float* __restrict__ ev,
    const float* __restrict__ nq, const float* __restrict__ nk,
    const float* __restrict__ naq,const float* __restrict__ nak,
    const float* __restrict__ cosr, const float* __restrict__ sinr,
    float* __restrict__ qf, float* __restrict__ kf, float* __restrict__ vf)
{
    const int s = blockIdx.x;       // 0..1535
    const int h = blockIdx.y;       // 0..23
    const int d = threadIdx.x;      // 0..127
    const int col = h * HD + d;

    const float *sq, *sk, *sv, *wq, *wk;
    if (s < S_TXT) {
        sq = eq + (size_t)s * HID; sk = ek + (size_t)s * HID; sv = ev + (size_t)s * HID;
        wq = naq; wk = nak;
    } else {
        int si = s - S_TXT;
        sq = q + (size_t)si * HID; sk = k + (size_t)si * HID; sv = v + (size_t)si * HID;
        wq = nq; wk = nk;
    }
    float xq = sq[col], xk = sk[col], xv = sv[col];

    __shared__ float red[8];
    float s2q = xq * xq, s2k = xk * xk;
#pragma unroll
    for (int o = 16; o; o >>= 1) {
        s2q += __shfl_xor_sync(0xffffffffu, s2q, o);
        s2k += __shfl_xor_sync(0xffffffffu, s2k, o);
    }
    int wid = d >> 5, lid = d & 31;
    if (lid == 0) { red[wid] = s2q; red[4 + wid] = s2k; }
    __syncthreads();
    float tq = red[0] + red[1] + red[2] + red[3];
    float tk = red[4] + red[5] + red[6] + red[7];
    float rq = rsqrtf(tq / (float)HD + EPS_F);
    float rk = rsqrtf(tk / (float)HD + EPS_F);
    float nxq = xq * rq * wq[d];
    float nxk = xk * rk * wk[d];

    __shared__ float shq[128], shk[128];
    shq[d] = nxq; shk[d] = nxk;
    __syncthreads();

    float c  = cosr[(size_t)s * HD + d];
    float sn = sinr[(size_t)s * HD + d];
    float oq, ok;
    if ((d & 1) == 0) {
        oq = nxq * c - shq[d + 1] * sn;
        ok = nxk * c - shk[d + 1] * sn;
    } else {
        oq = nxq * c + shq[d - 1] * sn;
        ok = nxk * c + shk[d - 1] * sn;
    }
    size_t o = ((size_t)h * S_TOT + s) * HD + d;
    qf[o] = oq; kf[o] = ok; vf[o] = xv;
}

// ---------------- main attention: flash-style, warp per query ----------------
__global__ __launch_bounds__(256) void attn_main(
    const float* __restrict__ qf, const float* __restrict__ kf,
    const float* __restrict__ vf, float* __restrict__ ctx)
{
    __shared__ float sK[32 * HD];
    __shared__ float sV[32 * HD];
    const int t = threadIdx.x, h = blockIdx.y;
    const int w = t >> 5, lane = t & 31;
    const int qs = blockIdx.x * 8 + w;

    float4 q4 = ((const float4*)(qf + ((size_t)h * S_TOT + qs) * HD))[lane];
    float m = -1e30f, l = 0.f;
    float4 acc = make_float4(0.f, 0.f, 0.f, 0.f);

    const float4* Kb = (const float4*)(kf + (size_t)h * S_TOT * HD);
    const float4* Vb = (const float4*)(vf + (size_t)h * S_TOT * HD);

    for (int kt = 0; kt < S_TOT / 32; kt++) {
#pragma unroll
        for (int i = 0; i < 4; i++) {
            ((float4*)sK)[t + i * 256] = Kb[kt * 1024 + t + i * 256];
            ((float4*)sV)[t + i * 256] = Vb[kt * 1024 + t + i * 256];
        }
        __syncthreads();
#pragma unroll 8
        for (int j = 0; j < 32; j++) {
            float4 kv = ((const float4*)sK)[j * 32 + lane];
            float d = q4.x * kv.x + q4.y * kv.y + q4.z * kv.z + q4.w * kv.w;
#pragma unroll
            for (int o = 16; o; o >>= 1) d += __shfl_xor_sync(0xffffffffu, d, o);
            float sc = d * SM_SCALE;
            float mn = fmaxf(m, sc);
            float corr = __expf(m - mn);
            float p = __expf(sc - mn);
            l = l * corr + p;
            float4 vv = ((const float4*)sV)[j * 32 + lane];
            acc.x = acc.x * corr + p * vv.x;
            acc.y = acc.y * corr + p * vv.y;
            acc.z = acc.z * corr + p * vv.z;
            acc.w = acc.w * corr + p * vv.w;
            m = mn;
        }
        __syncthreads();
    }
    float inv = 1.f / l;
    float4 out = make_float4(acc.x * inv, acc.y * inv, acc.z * inv, acc.w * inv);
    ((float4*)(ctx + (size_t)qs * HID + h * HD))[lane] = out;
}

// ---------------- IP attention: 16 keys, rms q/k in-kernel, accumulate into ctx ----------------
__global__ __launch_bounds__(256) void ip_attn(
    const float* __restrict__ q, const float* __restrict__ ipk, const float* __restrict__ ipv,
    const float* __restrict__ wqn, const float* __restrict__ wkn,
    float* __restrict__ ctx)
{
    __shared__ float sK[LIP * HD];
    __shared__ float sV[LIP * HD];
    const int t = threadIdx.x, h = blockIdx.y;
    const int w = t >> 5, lane = t & 31;

#pragma unroll
    for (int i = 0; i < 8; i++) {
        int idx = t + i * 256;
        int r = idx >> 7, c = idx & 127;
        sK[idx] = ipk[(size_t)r * HID + h * HD + c];
        sV[idx] = ipv[(size_t)r * HID + h * HD + c];
    }
    __syncthreads();

    float4 wk4 = *(const float4*)(wkn + lane * 4);
    // rms-normalize K rows: warp w handles rows w and w+8
    for (int rr = w; rr < LIP; rr += 8) {
        float4 kv = ((float4*)sK)[rr * 32 + lane];
        float ss = kv.x * kv.x + kv.y * kv.y + kv.z * kv.z + kv.w * kv.w;
#pragma unroll
        for (int o = 16; o; o >>= 1) ss += __shfl_xor_sync(0xffffffffu, ss, o);
        float r = rsqrtf(ss / (float)HD + EPS_F);
        kv.x *= r * wk4.x; kv.y *= r * wk4.y; kv.z *= r * wk4.z; kv.w *= r * wk4.w;
        ((float4*)sK)[rr * 32 + lane] = kv;
    }
    __syncthreads();

    const int s = blockIdx.x * 8 + w;   // image query index
    float4 q4 = *(const float4*)(q + (size_t)s * HID + h * HD + lane * 4);
    float ss = q4.x * q4.x + q4.y * q4.y + q4.z * q4.z + q4.w * q4.w;
#pragma unroll
    for (int o = 16; o; o >>= 1) ss += __shfl_xor_sync(0xffffffffu, ss, o);
    float rq = rsqrtf(ss / (float)HD + EPS_F);
    float4 wq4 = *(const float4*)(wqn + lane * 4);
    q4.x *= rq * wq4.x; q4.y *= rq * wq4.y; q4.z *= rq * wq4.z; q4.w *= rq * wq4.w;

    float sc[LIP];
#pragma unroll
    for (int j = 0; j < LIP; j++) {
        float4 kv = ((const float4*)sK)[j * 32 + lane];
        float d = q4.x * kv.x + q4.y * kv.y + q4.z * kv.z + q4.w * kv.w;
#pragma unroll
        for (int o = 16; o; o >>= 1) d += __shfl_xor_sync(0xffffffffu, d, o);
        sc[j] = d * SM_SCALE;
    }
    float mx = sc[0];
#pragma unroll
    for (int j = 1; j < LIP; j++) mx = fmaxf(mx, sc[j]);
    float l = 0.f;
#pragma unroll
    for (int j = 0; j < LIP; j++) { sc[j] = __expf(sc[j] - mx); l += sc[j]; }
    float inv = 1.f / l;

    float4 acc = make_float4(0.f, 0.f, 0.f, 0.f);
#pragma unroll
    for (int j = 0; j < LIP; j++) {
        float p = sc[j] * inv;
        float4 vv = ((const float4*)sV)[j * 32 + lane];
        acc.x += p * vv.x; acc.y += p * vv.y; acc.z += p * vv.z; acc.w += p * vv.w;
    }
    // img rows start at S_TXT in ctx; IP_SCALE == 1.0
    float* o = ctx + (size_t)(S_TXT + s) * HID + h * HD + lane * 4;
    float4 cur = *(float4*)o;
    cur.x += acc.x; cur.y += acc.y; cur.z += acc.z; cur.w += acc.w;
    *(float4*)o = cur;
}

// ---------------- host launch ----------------
static float* sym(const void* symbol) {
    void* p = nullptr;
    cudaGetSymbolAddress(&p, symbol);
    return (float*)p;
}

extern "C" void kernel_launch(void* const* d_in, const int* in_sizes, int n_in,
                              void* d_out, int out_size)
{
    const float* hs    = (const float*)d_in[0];
    const float* enc   = (const float*)d_in[1];
    const float* iph   = (const float*)d_in[2];
    const float* rcos  = (const float*)d_in[3];
    const float* rsin  = (const float*)d_in[4];
    const float* Wq    = (const float*)d_in[5];
    const float* bq    = (const float*)d_in[6];
    const float* Wk    = (const float*)d_in[7];
    const float* bk    = (const float*)d_in[8];
    const float* Wv    = (const float*)d_in[9];
    const float* bv    = (const float*)d_in[10];
    const float* nqw   = (const float*)d_in[11];
    const float* nkw   = (const float*)d_in[12];
    const float* Waq   = (const float*)d_in[13];
    const float* baq   = (const float*)d_in[14];
    const float* Wak   = (const float*)d_in[15];
    const float* bak   = (const float*)d_in[16];
    const float* Wav   = (const float*)d_in[17];
    const float* bav   = (const float*)d_in[18];
    const float* naqw  = (const float*)d_in[19];
    const float* nakw  = (const float*)d_in[20];
    const float* Wo    = (const float*)d_in[21];
    const float* bo    = (const float*)d_in[22];
    const float* Wadd  = (const float*)d_in[23];
    const float* badd  = (const float*)d_in[24];
    const float* Wkip  = (const float*)d_in[25];
    const float* bkip  = (const float*)d_in[26];
    const float* Wvip  = (const float*)d_in[27];
    const float* bvip  = (const float*)d_in[28];
    const float* nipq  = (const float*)d_in[29];
    const float* nipk  = (const float*)d_in[30];

    float* out = (float*)d_out;

    float* pq   = sym(g_q);   float* pk   = sym(g_k);   float* pv   = sym(g_v);
    float* peq  = sym(g_eq);  float* pek  = sym(g_ek);  float* pev  = sym(g_ev);
    float* pipk = sym(g_ipk); float* pipv = sym(g_ipv);
    float* pqf  = sym(g_qf);  float* pkf  = sym(g_kf);  float* pvf  = sym(g_vf);
    float* pctx = sym(g_ctx);

    dim3 blk(256);

    // projections
    sgemm_bias<<<dim3(HID / 128, S_IMG / 128), blk>>>(hs,  Wq,   bq,   pq,   S_IMG, HID, HID);
    sgemm_bias<<<dim3(HID / 128, S_IMG / 128), blk>>>(hs,  Wk,   bk,   pk,   S_IMG, HID, HID);
    sgemm_bias<<<dim3(HID / 128, S_IMG / 128), blk>>>(hs,  Wv,   bv,   pv,   S_IMG, HID, HID);
    sgemm_bias<<<dim3(HID / 128, S_TXT / 128), blk>>>(enc, Waq,  baq,  peq,  S_TXT, HID, HID);
    sgemm_bias<<<dim3(HID / 128, S_TXT / 128), blk>>>(enc, Wak,  bak,  pek,  S_TXT, HID, HID);
    sgemm_bias<<<dim3(HID / 128, S_TXT / 128), blk>>>(enc, Wav,  bav,  pev,  S_TXT, HID, HID);
    sgemm_bias<<<dim3(HID / 128, 1),           blk>>>(iph, Wkip, bkip, pipk, LIP,   IPD, HID);
    sgemm_bias<<<dim3(HID / 128, 1),           blk>>>(iph, Wvip, bvip, pipv, LIP,   IPD, HID);

    // rms + rope + head layout
    prepare_qkv<<<dim3(S_TOT, NH), 128>>>(pq, pk, pv, peq, pek, pev,
                                          nqw, nkw, naqw, nakw, rcos, rsin,
                                          pqf, pkf, pvf);

    // main attention (writes ctx), then IP attention (adds into img rows)
    attn_main<<<dim3(S_TOT / 8, NH), blk>>>(pqf, pkf, pvf, pctx);
    ip_attn<<<dim3(S_IMG / 8, NH), blk>>>(pq, pipk, pipv, nipq, nipk, pctx);

    // output projections: img_out first, then enc_out
    sgemm_bias<<<dim3(HID / 128, S_IMG / 128), blk>>>(pctx + (size_t)S_TXT * HID, Wo,   bo,   out,                        S_IMG, HID, HID);
    sgemm_bias<<<dim3(HID / 128, S_TXT / 128), blk>>>(pctx,                        Wadd, badd, out + (size_t)S_IMG * HID, S_TXT, HID, HID);
}

// round 4
// speedup vs baseline: 1.7913x; 1.7913x over previous
#include <cuda_runtime.h>
#include <cuda_bf16.h>
#include <cstdint>

// ---------------- problem constants ----------------
#define S_IMG 1024
#define S_TXT 512
#define S_TOT 1536
#define NH    24
#define HD    128
#define HID   3072
#define IPD   2048
#define LIP   16
#define EPS_F 1e-6f
#define SM_SCALE 0.08838834764831845f  // 1/sqrt(128)

// ---------------- fp32 scratch ----------------
__device__ float g_q [S_IMG * HID];
__device__ float g_k [S_IMG * HID];
__device__ float g_v [S_IMG * HID];
__device__ float g_eq[S_TXT * HID];
__device__ float g_ek[S_TXT * HID];
__device__ float g_ev[S_TXT * HID];
__device__ float g_ipk[LIP * HID];
__device__ float g_ipv[LIP * HID];
__device__ float g_qf[(size_t)NH * S_TOT * HD];
__device__ float g_kf[(size_t)NH * S_TOT * HD];
__device__ float g_vf[(size_t)NH * S_TOT * HD];
__device__ float g_ctx[(size_t)S_TOT * HID];

// ---------------- bf16 split scratch ----------------
__device__ __align__(16) __nv_bfloat16 g_hs_h [S_IMG * HID], g_hs_l [S_IMG * HID];
__device__ __align__(16) __nv_bfloat16 g_enc_h[S_TXT * HID], g_enc_l[S_TXT * HID];
__device__ __align__(16) __nv_bfloat16 g_iph_h[LIP * IPD],   g_iph_l[LIP * IPD];
__device__ __align__(16) __nv_bfloat16 g_ctxh [S_TOT * HID], g_ctxl [S_TOT * HID];
// transposed weights [N][K] bf16 hi/lo
__device__ __align__(16) __nv_bfloat16 g_WqT_h [HID * HID], g_WqT_l [HID * HID];
__device__ __align__(16) __nv_bfloat16 g_WkT_h [HID * HID], g_WkT_l [HID * HID];
__device__ __align__(16) __nv_bfloat16 g_WvT_h [HID * HID], g_WvT_l [HID * HID];
__device__ __align__(16) __nv_bfloat16 g_WaqT_h[HID * HID], g_WaqT_l[HID * HID];
__device__ __align__(16) __nv_bfloat16 g_WakT_h[HID * HID], g_WakT_l[HID * HID];
__device__ __align__(16) __nv_bfloat16 g_WavT_h[HID * HID], g_WavT_l[HID * HID];
__device__ __align__(16) __nv_bfloat16 g_WoT_h [HID * HID], g_WoT_l [HID * HID];
__device__ __align__(16) __nv_bfloat16 g_WadT_h[HID * HID], g_WadT_l[HID * HID];
__device__ __align__(16) __nv_bfloat16 g_WkiT_h[HID * IPD], g_WkiT_l[HID * IPD];
__device__ __align__(16) __nv_bfloat16 g_WviT_h[HID * IPD], g_WviT_l[HID * IPD];

// ---------------- low-level helpers (sm_80+ portable) ----------------
__device__ __forceinline__ uint32_t smem_u32(const void* p) {
    return (uint32_t)__cvta_generic_to_shared(p);
}
__device__ __forceinline__ void cpa16(uint32_t dst, const void* src, int sz) {
    asm volatile("cp.async.cg.shared.global [%0], [%1], 16, %2;"
                 :: "r"(dst), "l"(src), "r"(sz) : "memory");
}
__device__ __forceinline__ void cp_commit() {
    asm volatile("cp.async.commit_group;" ::: "memory");
}
template<int N> __device__ __forceinline__ void cp_wait() {
    asm volatile("cp.async.wait_group %0;" :: "n"(N) : "memory");
}
__device__ __forceinline__ void ldsm4(uint32_t* r, uint32_t addr) {
    asm volatile("ldmatrix.sync.aligned.m8n8.x4.shared.b16 {%0,%1,%2,%3}, [%4];"
                 : "=r"(r[0]), "=r"(r[1]), "=r"(r[2]), "=r"(r[3]) : "r"(addr));
}
__device__ __forceinline__ void mma_bf16(float* c, const uint32_t* a, const uint32_t* b) {
    asm volatile(
        "mma.sync.aligned.m16n8k16.row.col.f32.bf16.bf16.f32 "
        "{%0,%1,%2,%3}, {%4,%5,%6,%7}, {%8,%9}, {%0,%1,%2,%3};"
        : "+f"(c[0]), "+f"(c[1]), "+f"(c[2]), "+f"(c[3])
        : "r"(a[0]), "r"(a[1]), "r"(a[2]), "r"(a[3]), "r"(b[0]), "r"(b[1]));
}

struct GemmSet { const __nv_bfloat16* bh; const __nv_bfloat16* bl;
                 const float* bias; float* out; };

// ---------------- mma.sync bf16x3 GEMM ----------------
// C[M, 3072] = A[M,K] @ W^T[N,K]^T + bias.  128x128 CTA tile, BK=32, 8 warps.
// Smem tile: [128 rows][40 halfs] (80B pitch -> conflict-free ldmatrix).
#define TILE_B  10240                 // 128*40*2 bytes
#define STAGE_B (4 * TILE_B)          // AH, AL, BH, BL
#define GEMM_SMEM (2 * STAGE_B)       // double buffered = 81920 B

__global__ __launch_bounds__(256) void gemm_mma(
    const __nv_bfloat16* __restrict__ Ahi, const __nv_bfloat16* __restrict__ Alo,
    GemmSet s0, GemmSet s1, GemmSet s2, int M, int K)
{
    extern __shared__ char smem[];
    const uint32_t sb = smem_u32(smem);
    const int tid = threadIdx.x, warp = tid >> 5, lane = tid & 31;
    const GemmSet S = (blockIdx.z == 0) ? s0 : ((blockIdx.z == 1) ? s1 : s2);
    const int nb = blockIdx.x, mb = blockIdx.y;
    const int wm = warp & 3, wn = warp >> 2;       // warp tile: 32m x 64n

    const __nv_bfloat16* gAh = Ahi  + (size_t)mb * 128 * K;
    const __nv_bfloat16* gAl = Alo  + (size_t)mb * 128 * K;
    const __nv_bfloat16* gBh = S.bh + (size_t)nb * 128 * K;
    const __nv_bfloat16* gBl = S.bl + (size_t)nb * 128 * K;
    const int rows_a = min(128, M - mb * 128);

    // cp.async assignment: thread t loads row t/2, halfs (t&1)*16 .. +15 (two 16B)
    const int r  = tid >> 1;
    const int hc = (tid & 1) * 16;
    const bool av = r < rows_a;
    const int asz = av ? 16 : 0;
    const uint32_t dst_ro = (uint32_t)(r * 80 + hc * 2);

    auto issue = [&](int kc, int st) {
        size_t go = (size_t)r * K + (size_t)kc * 32 + hc;
        uint32_t d = sb + st * STAGE_B + dst_ro;
        const __nv_bfloat16* pa = av ? (gAh + go) : gAh;
        const __nv_bfloat16* pl = av ? (gAl + go) : gAl;
        cpa16(d,                 pa,     asz);
        cpa16(d + 16,            pa + 8, asz);
        cpa16(d + TILE_B,        pl,     asz);
        cpa16(d + TILE_B + 16,   pl + 8, asz);
        cpa16(d + 2 * TILE_B,      gBh + go,     16);
        cpa16(d + 2 * TILE_B + 16, gBh + go + 8, 16);
        cpa16(d + 3 * TILE_B,      gBl + go,     16);
        cpa16(d + 3 * TILE_B + 16, gBl + go + 8, 16);
        cp_commit();
    };

    float c[2][8][4];
#pragma unroll
    for (int i = 0; i < 2; i++)
#pragma unroll
        for (int j = 0; j < 8; j++)
#pragma unroll
            for (int e = 0; e < 4; e++) c[i][j][e] = 0.f;

    const int nch = K / 32;
    issue(0, 0);

    // precomputed ldmatrix intra-tile offsets
    const int a_r  = wm * 32 + (lane & 15);
    const int a_c8 = (lane >> 4) * 8;
    const int b_n  = wn * 64 + (lane >> 4) * 8 + (lane & 7);
    const int b_c8 = ((lane >> 3) & 1) * 8;

    for (int kc = 0; kc < nch; kc++) {
        const int st = kc & 1;
        if (kc + 1 < nch) { issue(kc + 1, st ^ 1); cp_wait<1>(); }
        else              { cp_wait<0>(); }
        __syncthreads();

        const uint32_t sa = sb + st * STAGE_B;
#pragma unroll
        for (int ks = 0; ks < 2; ks++) {
            uint32_t ah[2][4], al[2][4];
#pragma unroll
            for (int mf = 0; mf < 2; mf++) {
                uint32_t ad = sa + (uint32_t)((a_r + mf * 16) * 80 + (ks * 16 + a_c8) * 2);
                ldsm4(ah[mf], ad);
                ldsm4(al[mf], ad + TILE_B);
            }
            uint32_t bh[8][2], bl[8][2];
#pragma unroll
            for (int nf = 0; nf < 4; nf++) {
                uint32_t bd = sa + 2 * TILE_B +
                              (uint32_t)((b_n + nf * 16) * 80 + (ks * 16 + b_c8) * 2);
                uint32_t t0[4], t1[4];
                ldsm4(t0, bd);
                ldsm4(t1, bd + TILE_B);
                bh[nf * 2][0] = t0[0]; bh[nf * 2][1] = t0[1];
                bh[nf * 2 + 1][0] = t0[2]; bh[nf * 2 + 1][1] = t0[3];
                bl[nf * 2][0] = t1[0]; bl[nf * 2][1] = t1[1];
                bl[nf * 2 + 1][0] = t1[2]; bl[nf * 2 + 1][1] = t1[3];
            }
#pragma unroll
            for (int mf = 0; mf < 2; mf++)
#pragma unroll
                for (int nf = 0; nf < 8; nf++) {
                    mma_bf16(c[mf][nf], ah[mf], bh[nf]);
                    mma_bf16(c[mf][nf], ah[mf], bl[nf]);
                    mma_bf16(c[mf][nf], al[mf], bh[nf]);
                }
        }
        __syncthreads();
    }

    // epilogue
#pragma unroll
    for (int mf = 0; mf < 2; mf++) {
#pragma unroll
        for (int nf = 0; nf < 8; nf++) {
            int row0 = mb * 128 + wm * 32 + mf * 16 + (lane >> 2);
            int col  = nb * 128 + wn * 64 + nf * 8 + (lane & 3) * 2;
            float b0 = S.bias[col], b1 = S.bias[col + 1];
            if (row0 < M) {
                float2 o0 = make_float2(c[mf][nf][0] + b0, c[mf][nf][1] + b1);
                *(float2*)(S.out + (size_t)row0 * HID + col) = o0;
            }
            int row1 = row0 + 8;
            if (row1 < M) {
                float2 o1 = make_float2(c[mf][nf][2] + b0, c[mf][nf][3] + b1);
                *(float2*)(S.out + (size_t)row1 * HID + col) = o1;
            }
        }
    }
}

// ---------------- fp32 -> bf16 hi/lo split (elementwise) ----------------
__global__ __launch_bounds__(256) void conv_act(
    const float* __restrict__ x, __nv_bfloat16* __restrict__ h,
    __nv_bfloat16* __restrict__ l, int n4)
{
    int i = blockIdx.x * 256 + threadIdx.x;
    if (i >= n4) return;
    float4 v = ((const float4*)x)[i];
    __nv_bfloat16 h0 = __float2bfloat16(v.x), h1 = __float2bfloat16(v.y);
    __nv_bfloat16 h2 = __float2bfloat16(v.z), h3 = __float2bfloat16(v.w);
    __nv_bfloat16 l0 = __float2bfloat16(v.x - __bfloat162float(h0));
    __nv_bfloat16 l1 = __float2bfloat16(v.y - __bfloat162float(h1));
    __nv_bfloat16 l2 = __float2bfloat16(v.z - __bfloat162float(h2));
    __nv_bfloat16 l3 = __float2bfloat16(v.w - __bfloat162float(h3));
    ((__nv_bfloat162*)h)[2 * i]     = __nv_bfloat162(h0, h1);
    ((__nv_bfloat162*)h)[2 * i + 1] = __nv_bfloat162(h2, h3);
    ((__nv_bfloat162*)l)[2 * i]     = __nv_bfloat162(l0, l1);
    ((__nv_bfloat162*)l)[2 * i + 1] = __nv_bfloat162(l2, l3);
}

// ---------------- W[K][N] fp32 -> W^T[N][K] bf16 hi/lo ----------------
__global__ __launch_bounds__(256) void conv_wT(
    const float* __restrict__ W, __nv_bfloat16* __restrict__ th,
    __nv_bfloat16* __restrict__ tl, int K, int N)
{
    __shared__ float s[32][33];
    const int tx = threadIdx.x & 31, ty = threadIdx.x >> 5;
    const int k0 = blockIdx.y * 32, n0 = blockIdx.x * 32;
#pragma unroll
    for (int r = 0; r < 4; r++)
        s[ty + r * 8][tx] = W[(size_t)(k0 + ty + r * 8) * N + n0 + tx];
    __syncthreads();
#pragma unroll
    for (int r = 0; r < 4; r++) {
        int n = n0 + ty + r * 8, k = k0 + tx;
        float v = s[tx][ty + r * 8];
        __nv_bfloat16 h = __float2bfloat16(v);
        th[(size_t)n * K + k] = h;
        tl[(size_t)n * K + k] = __float2bfloat16(v - __bfloat162float(h));
    }
}

// ---------------- prepare: rms-norm + rope on q/k, copy v, into [H][S][D] ----------------
__global__ __launch_bounds__(128) void prepare_qkv(
    const float* __restrict__ q,  const float* __restrict__ k,  const float* __restrict__ v,
    const float* __restrict__ eq, const float* __restrict__ ek, const float* __restrict__ ev,
    const float* __restrict__ nq, const float* __restrict__ nk,
    const float* __restrict__ naq,const float* __restrict__ nak,
    const float* __restrict__ cosr, const float* __restrict__ sinr,
    float* __restrict__ qf, float* __restrict__ kf, float* __restrict__ vf)
{
    const int s = blockIdx.x;
    const int h = blockIdx.y;
    const int d = threadIdx.x;
    const int col = h * HD + d;

    const float *sq, *sk, *sv, *wq, *wk;
    if (s < S_TXT) {
        sq = eq + (size_t)s * HID; sk = ek + (size_t)s * HID; sv = ev + (size_t)s * HID;
        wq = naq; wk = nak;
    } else {
        int si = s - S_TXT;
        sq = q + (size_t)si * HID; sk = k + (size_t)si * HID; sv = v + (size_t)si * HID;
        wq = nq; wk = nk;
    }
    float xq = sq[col], xk = sk[col], xv = sv[col];

    __shared__ float red[8];
    float s2q = xq * xq, s2k = xk * xk;
#pragma unroll
    for (int o = 16; o; o >>= 1) {
        s2q += __shfl_xor_sync(0xffffffffu, s2q, o);
        s2k += __shfl_xor_sync(0xffffffffu, s2k, o);
    }
    int wid = d >> 5, lid = d & 31;
    if (lid == 0) { red[wid] = s2q; red[4 + wid] = s2k; }
    __syncthreads();
    float tq = red[0] + red[1] + red[2] + red[3];
    float tk = red[4] + red[5] + red[6] + red[7];
    float rq = rsqrtf(tq / (float)HD + EPS_F);
    float rk = rsqrtf(tk / (float)HD + EPS_F);
    float nxq = xq * rq * wq[d];
    float nxk = xk * rk * wk[d];

    __shared__ float shq[128], shk[128];
    shq[d] = nxq; shk[d] = nxk;
    __syncthreads();

    float c  = cosr[(size_t)s * HD + d];
    float sn = sinr[(size_t)s * HD + d];
    float oq, ok;
    if ((d & 1) == 0) {
        oq = nxq * c - shq[d + 1] * sn;
        ok = nxk * c - shk[d + 1] * sn;
    } else {
        oq = nxq * c + shq[d - 1] * sn;
        ok = nxk * c + shk[d - 1] * sn;
    }
    size_t o = ((size_t)h * S_TOT + s) * HD + d;
    qf[o] = oq; kf[o] = ok; vf[o] = xv;
}

// ---------------- main attention: flash-style, warp per query ----------------
__global__ __launch_bounds__(256) void attn_main(
    const float* __restrict__ qf, const float* __restrict__ kf,
    const float* __restrict__ vf, float* __restrict__ ctx)
{
    __shared__ float sK[32 * HD];
    __shared__ float sV[32 * HD];
    const int t = threadIdx.x, h = blockIdx.y;
    const int w = t >> 5, lane = t & 31;
    const int qs = blockIdx.x * 8 + w;

    float4 q4 = ((const float4*)(qf + ((size_t)h * S_TOT + qs) * HD))[lane];
    float m = -1e30f, l = 0.f;
    float4 acc = make_float4(0.f, 0.f, 0.f, 0.f);

    const float4* Kb = (const float4*)(kf + (size_t)h * S_TOT * HD);
    const float4* Vb = (const float4*)(vf + (size_t)h * S_TOT * HD);

    for (int kt = 0; kt < S_TOT / 32; kt++) {
#pragma unroll
        for (int i = 0; i < 4; i++) {
            ((float4*)sK)[t + i * 256] = Kb[kt * 1024 + t + i * 256];
            ((float4*)sV)[t + i * 256] = Vb[kt * 1024 + t + i * 256];
        }
        __syncthreads();
#pragma unroll 8
        for (int j = 0; j < 32; j++) {
            float4 kv = ((const float4*)sK)[j * 32 + lane];
            float d = q4.x * kv.x + q4.y * kv.y + q4.z * kv.z + q4.w * kv.w;
#pragma unroll
            for (int o = 16; o; o >>= 1) d += __shfl_xor_sync(0xffffffffu, d, o);
            float sc = d * SM_SCALE;
            float mn = fmaxf(m, sc);
            float corr = __expf(m - mn);
            float p = __expf(sc - mn);
            l = l * corr + p;
            float4 vv = ((const float4*)sV)[j * 32 + lane];
            acc.x = acc.x * corr + p * vv.x;
            acc.y = acc.y * corr + p * vv.y;
            acc.z = acc.z * corr + p * vv.z;
            acc.w = acc.w * corr + p * vv.w;
            m = mn;
        }
        __syncthreads();
    }
    float inv = 1.f / l;
    float4 out = make_float4(acc.x * inv, acc.y * inv, acc.z * inv, acc.w * inv);
    ((float4*)(ctx + (size_t)qs * HID + h * HD))[lane] = out;
}

// ---------------- IP attention ----------------
__global__ __launch_bounds__(256) void ip_attn(
    const float* __restrict__ q, const float* __restrict__ ipk, const float* __restrict__ ipv,
    const float* __restrict__ wqn, const float* __restrict__ wkn,
    float* __restrict__ ctx)
{
    __shared__ float sK[LIP * HD];
    __shared__ float sV[LIP * HD];
    const int t = threadIdx.x, h = blockIdx.y;
    const int w = t >> 5, lane = t & 31;

#pragma unroll
    for (int i = 0; i < 8; i++) {
        int idx = t + i * 256;
        int r = idx >> 7, c = idx & 127;
        sK[idx] = ipk[(size_t)r * HID + h * HD + c];
        sV[idx] = ipv[(size_t)r * HID + h * HD + c];
    }
    __syncthreads();

    float4 wk4 = *(const float4*)(wkn + lane * 4);
    for (int rr = w; rr < LIP; rr += 8) {
        float4 kv = ((float4*)sK)[rr * 32 + lane];
        float ss = kv.x * kv.x + kv.y * kv.y + kv.z * kv.z + kv.w * kv.w;
#pragma unroll
        for (int o = 16; o; o >>= 1) ss += __shfl_xor_sync(0xffffffffu, ss, o);
        float r = rsqrtf(ss / (float)HD + EPS_F);
        kv.x *= r * wk4.x; kv.y *= r * wk4.y; kv.z *= r * wk4.z; kv.w *= r * wk4.w;
        ((float4*)sK)[rr * 32 + lane] = kv;
    }
    __syncthreads();

    const int s = blockIdx.x * 8 + w;
    float4 q4 = *(const float4*)(q + (size_t)s * HID + h * HD + lane * 4);
    float ss = q4.x * q4.x + q4.y * q4.y + q4.z * q4.z + q4.w * q4.w;
#pragma unroll
    for (int o = 16; o; o >>= 1) ss += __shfl_xor_sync(0xffffffffu, ss, o);
    float rq = rsqrtf(ss / (float)HD + EPS_F);
    float4 wq4 = *(const float4*)(wqn + lane * 4);
    q4.x *= rq * wq4.x; q4.y *= rq * wq4.y; q4.z *= rq * wq4.z; q4.w *= rq * wq4.w;

    float sc[LIP];
#pragma unroll
    for (int j = 0; j < LIP; j++) {
        float4 kv = ((const float4*)sK)[j * 32 + lane];
        float d = q4.x * kv.x + q4.y * kv.y + q4.z * kv.z + q4.w * kv.w;
#pragma unroll
        for (int o = 16; o; o >>= 1) d += __shfl_xor_sync(0xffffffffu, d, o);
        sc[j] = d * SM_SCALE;
    }
    float mx = sc[0];
#pragma unroll
    for (int j = 1; j < LIP; j++) mx = fmaxf(mx, sc[j]);
    float l = 0.f;
#pragma unroll
    for (int j = 0; j < LIP; j++) { sc[j] = __expf(sc[j] - mx); l += sc[j]; }
    float inv = 1.f / l;

    float4 acc = make_float4(0.f, 0.f, 0.f, 0.f);
#pragma unroll
    for (int j = 0; j < LIP; j++) {
        float p = sc[j] * inv;
        float4 vv = ((const float4*)sV)[j * 32 + lane];
        acc.x += p * vv.x; acc.y += p * vv.y; acc.z += p * vv.z; acc.w += p * vv.w;
    }
    float* o = ctx + (size_t)(S_TXT + s) * HID + h * HD + lane * 4;
    float4 cur = *(float4*)o;
    cur.x += acc.x; cur.y += acc.y; cur.z += acc.z; cur.w += acc.w;
    *(float4*)o = cur;
}

// ---------------- host launch ----------------
static float* symf(const void* s) { void* p = nullptr; cudaGetSymbolAddress(&p, s); return (float*)p; }
static __nv_bfloat16* symb(const void* s) { void* p = nullptr; cudaGetSymbolAddress(&p, s); return (__nv_bfloat16*)p; }

extern "C" void kernel_launch(void* const* d_in, const int* in_sizes, int n_in,
                              void* d_out, int out_size)
{
    const float* hs    = (const float*)d_in[0];
    const float* enc   = (const float*)d_in[1];
    const float* iph   = (const float*)d_in[2];
    const float* rcos  = (const float*)d_in[3];
    const float* rsin  = (const float*)d_in[4];
    const float* Wq    = (const float*)d_in[5];
    const float* bq    = (const float*)d_in[6];
    const float* Wk    = (const float*)d_in[7];
    const float* bk    = (const float*)d_in[8];
    const float* Wv    = (const float*)d_in[9];
    const float* bv    = (const float*)d_in[10];
    const float* nqw   = (const float*)d_in[11];
    const float* nkw   = (const float*)d_in[12];
    const float* Waq   = (const float*)d_in[13];
    const float* baq   = (const float*)d_in[14];
    const float* Wak   = (const float*)d_in[15];
    const float* bak   = (const float*)d_in[16];
    const float* Wav   = (const float*)d_in[17];
    const float* bav   = (const float*)d_in[18];
    const float* naqw  = (const float*)d_in[19];
    const float* nakw  = (const float*)d_in[20];
    const float* Wo    = (const float*)d_in[21];
    const float* bo    = (const float*)d_in[22];
    const float* Wadd  = (const float*)d_in[23];
    const float* badd  = (const float*)d_in[24];
    const float* Wkip  = (const float*)d_in[25];
    const float* bkip  = (const float*)d_in[26];
    const float* Wvip  = (const float*)d_in[27];
    const float* bvip  = (const float*)d_in[28];
    const float* nipq  = (const float*)d_in[29];
    const float* nipk  = (const float*)d_in[30];

    float* out = (float*)d_out;

    float* pq   = symf(g_q);   float* pk   = symf(g_k);   float* pv   = symf(g_v);
    float* peq  = symf(g_eq);  float* pek  = symf(g_ek);  float* pev  = symf(g_ev);
    float* pipk = symf(g_ipk); float* pipv = symf(g_ipv);
    float* pqf  = symf(g_qf);  float* pkf  = symf(g_kf);  float* pvf  = symf(g_vf);
    float* pctx = symf(g_ctx);

    __nv_bfloat16 *hsh = symb(g_hs_h),  *hsl = symb(g_hs_l);
    __nv_bfloat16 *ech = symb(g_enc_h), *ecl = symb(g_enc_l);
    __nv_bfloat16 *iph_h = symb(g_iph_h), *iph_l = symb(g_iph_l);
    __nv_bfloat16 *cxh = symb(g_ctxh),  *cxl = symb(g_ctxl);
    __nv_bfloat16 *wq_h = symb(g_WqT_h),  *wq_l = symb(g_WqT_l);
    __nv_bfloat16 *wk_h = symb(g_WkT_h),  *wk_l = symb(g_WkT_l);
    __nv_bfloat16 *wv_h = symb(g_WvT_h),  *wv_l = symb(g_WvT_l);
    __nv_bfloat16 *waq_h = symb(g_WaqT_h), *waq_l = symb(g_WaqT_l);
    __nv_bfloat16 *wak_h = symb(g_WakT_h), *wak_l = symb(g_WakT_l);
    __nv_bfloat16 *wav_h = symb(g_WavT_h), *wav_l = symb(g_WavT_l);
    __nv_bfloat16 *wo_h = symb(g_WoT_h),  *wo_l = symb(g_WoT_l);
    __nv_bfloat16 *wad_h = symb(g_WadT_h), *wad_l = symb(g_WadT_l);
    __nv_bfloat16 *wki_h = symb(g_WkiT_h), *wki_l = symb(g_WkiT_l);
    __nv_bfloat16 *wvi_h = symb(g_WviT_h), *wvi_l = symb(g_WviT_l);

    cudaFuncSetAttribute(gemm_mma, cudaFuncAttributeMaxDynamicSharedMemorySize, GEMM_SMEM);

    // -------- conversions --------
    conv_act<<<(S_IMG * HID / 4 + 255) / 256, 256>>>(hs,  hsh, hsl, S_IMG * HID / 4);
    conv_act<<<(S_TXT * HID / 4 + 255) / 256, 256>>>(enc, ech, ecl, S_TXT * HID / 4);
    conv_act<<<(LIP * IPD / 4 + 255) / 256, 256>>>(iph, iph_h, iph_l, LIP * IPD / 4);

    dim3 wg(HID / 32, HID / 32);
    conv_wT<<<wg, 256>>>(Wq,   wq_h,  wq_l,  HID, HID);
    conv_wT<<<wg, 256>>>(Wk,   wk_h,  wk_l,  HID, HID);
    conv_wT<<<wg, 256>>>(Wv,   wv_h,  wv_l,  HID, HID);
    conv_wT<<<wg, 256>>>(Waq,  waq_h, waq_l, HID, HID);
    conv_wT<<<wg, 256>>>(Wak,  wak_h, wak_l, HID, HID);
    conv_wT<<<wg, 256>>>(Wav,  wav_h, wav_l, HID, HID);
    conv_wT<<<wg, 256>>>(Wo,   wo_h,  wo_l,  HID, HID);
    conv_wT<<<wg, 256>>>(Wadd, wad_h, wad_l, HID, HID);
    dim3 wgip(HID / 32, IPD / 32);
    conv_wT<<<wgip, 256>>>(Wkip, wki_h, wki_l, IPD, HID);
    conv_wT<<<wgip, 256>>>(Wvip, wvi_h, wvi_l, IPD, HID);

    // -------- projections (mma.sync bf16x3) --------
    GemmSet sq{wq_h, wq_l, bq, pq}, sk{wk_h, wk_l, bk, pk}, sv{wv_h, wv_l, bv, pv};
    gemm_mma<<<dim3(HID / 128, S_IMG / 128, 3), 256, GEMM_SMEM>>>(hsh, hsl, sq, sk, sv, S_IMG, HID);

    GemmSet se1{waq_h, waq_l, baq, peq}, se2{wak_h, wak_l, bak, pek}, se3{wav_h, wav_l, bav, pev};
    gemm_mma<<<dim3(HID / 128, S_TXT / 128, 3), 256, GEMM_SMEM>>>(ech, ecl, se1, se2, se3, S_TXT, HID);

    GemmSet si1{wki_h, wki_l, bkip, pipk}, si2{wvi_h, wvi_l, bvip, pipv};
    gemm_mma<<<dim3(HID / 128, 1, 2), 256, GEMM_SMEM>>>(iph_h, iph_l, si1, si2, si1, LIP, IPD);

    // -------- rms + rope + head layout --------
    prepare_qkv<<<dim3(S_TOT, NH), 128>>>(pq, pk, pv, peq, pek, pev,
                                          nqw, nkw, naqw, nakw, rcos, rsin,
                                          pqf, pkf, pvf);

    // -------- attention --------
    attn_main<<<dim3(S_TOT / 8, NH), 256>>>(pqf, pkf, pvf, pctx);
    ip_attn<<<dim3(S_IMG / 8, NH), 256>>>(pq, symf(g_ipk), symf(g_ipv), nipq, nipk, pctx);

    // -------- output projections --------
    conv_act<<<(S_TOT * HID / 4 + 255) / 256, 256>>>(pctx, cxh, cxl, S_TOT * HID / 4);

    GemmSet so{wo_h, wo_l, bo, out};
    gemm_mma<<<dim3(HID / 128, S_IMG / 128, 1), 256, GEMM_SMEM>>>(
        cxh + (size_t)S_TXT * HID, cxl + (size_t)S_TXT * HID, so, so, so, S_IMG, HID);

    GemmSet sa{wad_h, wad_l, badd, out + (size_t)S_IMG * HID};
    gemm_mma<<<dim3(HID / 128, S_TXT / 128, 1), 256, GEMM_SMEM>>>(
        cxh, cxl, sa, sa, sa, S_TXT, HID);
}

// round 5
// speedup vs baseline: 4.3332x; 2.4190x over previous
#include <cuda_runtime.h>
#include <cuda_bf16.h>
#include <cstdint>

// ---------------- problem constants ----------------
#define S_IMG 1024
#define S_TXT 512
#define S_TOT 1536
#define NH    24
#define HD    128
#define HID   3072
#define IPD   2048
#define LIP   16
#define EPS_F 1e-6f
#define SM_SCALE 0.08838834764831845f  // 1/sqrt(128)

// ---------------- fp32 scratch ----------------
__device__ float g_q [S_IMG * HID];
__device__ float g_k [S_IMG * HID];
__device__ float g_v [S_IMG * HID];
__device__ float g_eq[S_TXT * HID];
__device__ float g_ek[S_TXT * HID];
__device__ float g_ev[S_TXT * HID];
__device__ float g_ipk[LIP * HID];
__device__ float g_ipv[LIP * HID];
__device__ float g_ctx[(size_t)S_TOT * HID];

// bf16 hi/lo q/k/v in [H][S][D] layout (q pre-scaled by SM_SCALE)
__device__ __align__(16) __nv_bfloat16 g_qh[(size_t)NH * S_TOT * HD], g_ql[(size_t)NH * S_TOT * HD];
__device__ __align__(16) __nv_bfloat16 g_kh[(size_t)NH * S_TOT * HD], g_kl[(size_t)NH * S_TOT * HD];
__device__ __align__(16) __nv_bfloat16 g_vh[(size_t)NH * S_TOT * HD], g_vl[(size_t)NH * S_TOT * HD];

// ---------------- bf16 split scratch ----------------
__device__ __align__(16) __nv_bfloat16 g_hs_h [S_IMG * HID], g_hs_l [S_IMG * HID];
__device__ __align__(16) __nv_bfloat16 g_enc_h[S_TXT * HID], g_enc_l[S_TXT * HID];
__device__ __align__(16) __nv_bfloat16 g_iph_h[LIP * IPD],   g_iph_l[LIP * IPD];
__device__ __align__(16) __nv_bfloat16 g_ctxh [S_TOT * HID], g_ctxl [S_TOT * HID];
// transposed weights [N][K] bf16 hi/lo
__device__ __align__(16) __nv_bfloat16 g_WqT_h [HID * HID], g_WqT_l [HID * HID];
__device__ __align__(16) __nv_bfloat16 g_WkT_h [HID * HID], g_WkT_l [HID * HID];
__device__ __align__(16) __nv_bfloat16 g_WvT_h [HID * HID], g_WvT_l [HID * HID];
__device__ __align__(16) __nv_bfloat16 g_WaqT_h[HID * HID], g_WaqT_l[HID * HID];
__device__ __align__(16) __nv_bfloat16 g_WakT_h[HID * HID], g_WakT_l[HID * HID];
__device__ __align__(16) __nv_bfloat16 g_WavT_h[HID * HID], g_WavT_l[HID * HID];
__device__ __align__(16) __nv_bfloat16 g_WoT_h [HID * HID], g_WoT_l [HID * HID];
__device__ __align__(16) __nv_bfloat16 g_WadT_h[HID * HID], g_WadT_l[HID * HID];
__device__ __align__(16) __nv_bfloat16 g_WkiT_h[HID * IPD], g_WkiT_l[HID * IPD];
__device__ __align__(16) __nv_bfloat16 g_WviT_h[HID * IPD], g_WviT_l[HID * IPD];

// ---------------- low-level helpers ----------------
__device__ __forceinline__ uint32_t smem_u32(const void* p) {
    return (uint32_t)__cvta_generic_to_shared(p);
}
__device__ __forceinline__ void cpa16(uint32_t dst, const void* src, int sz) {
    asm volatile("cp.async.cg.shared.global [%0], [%1], 16, %2;"
                 :: "r"(dst), "l"(src), "r"(sz) : "memory");
}
__device__ __forceinline__ void cp_commit() {
    asm volatile("cp.async.commit_group;" ::: "memory");
}
template<int N> __device__ __forceinline__ void cp_wait() {
    asm volatile("cp.async.wait_group %0;" :: "n"(N) : "memory");
}
__device__ __forceinline__ void ldsm4(uint32_t* r, uint32_t addr) {
    asm volatile("ldmatrix.sync.aligned.m8n8.x4.shared.b16 {%0,%1,%2,%3}, [%4];"
                 : "=r"(r[0]), "=r"(r[1]), "=r"(r[2]), "=r"(r[3]) : "r"(addr));
}
__device__ __forceinline__ void ldsm4t(uint32_t* r, uint32_t addr) {
    asm volatile("ldmatrix.sync.aligned.m8n8.x4.trans.shared.b16 {%0,%1,%2,%3}, [%4];"
                 : "=r"(r[0]), "=r"(r[1]), "=r"(r[2]), "=r"(r[3]) : "r"(addr));
}
__device__ __forceinline__ void mma_bf16(float* c, const uint32_t* a, const uint32_t* b) {
    asm volatile(
        "mma.sync.aligned.m16n8k16.row.col.f32.bf16.bf16.f32 "
        "{%0,%1,%2,%3}, {%4,%5,%6,%7}, {%8,%9}, {%0,%1,%2,%3};"
        : "+f"(c[0]), "+f"(c[1]), "+f"(c[2]), "+f"(c[3])
        : "r"(a[0]), "r"(a[1]), "r"(a[2]), "r"(a[3]), "r"(b[0]), "r"(b[1]));
}
__device__ __forceinline__ void mma_bf16s(float* c, const uint32_t* a, uint32_t b0, uint32_t b1) {
    asm volatile(
        "mma.sync.aligned.m16n8k16.row.col.f32.bf16.bf16.f32 "
        "{%0,%1,%2,%3}, {%4,%5,%6,%7}, {%8,%9}, {%0,%1,%2,%3};"
        : "+f"(c[0]), "+f"(c[1]), "+f"(c[2]), "+f"(c[3])
        : "r"(a[0]), "r"(a[1]), "r"(a[2]), "r"(a[3]), "r"(b0), "r"(b1));
}
__device__ __forceinline__ uint32_t packbf(float a, float b) {
    __nv_bfloat162 t = __floats2bfloat162_rn(a, b);
    return *(uint32_t*)&t;
}

struct GemmSet { const __nv_bfloat16* bh; const __nv_bfloat16* bl;
                 const float* bias; float* out; };

// ---------------- mma.sync bf16x3 GEMM (unchanged, validated R4) ----------------
#define TILE_B  10240
#define STAGE_B (4 * TILE_B)
#define GEMM_SMEM (2 * STAGE_B)

__global__ __launch_bounds__(256) void gemm_mma(
    const __nv_bfloat16* __restrict__ Ahi, const __nv_bfloat16* __restrict__ Alo,
    GemmSet s0, GemmSet s1, GemmSet s2, int M, int K)
{
    extern __shared__ char smem[];
    const uint32_t sb = smem_u32(smem);
    const int tid = threadIdx.x, warp = tid >> 5, lane = tid & 31;
    const GemmSet S = (blockIdx.z == 0) ? s0 : ((blockIdx.z == 1) ? s1 : s2);
    const int nb = blockIdx.x, mb = blockIdx.y;
    const int wm = warp & 3, wn = warp >> 2;

    const __nv_bfloat16* gAh = Ahi  + (size_t)mb * 128 * K;
    const __nv_bfloat16* gAl = Alo  + (size_t)mb * 128 * K;
    const __nv_bfloat16* gBh = S.bh + (size_t)nb * 128 * K;
    const __nv_bfloat16* gBl = S.bl + (size_t)nb * 128 * K;
    const int rows_a = min(128, M - mb * 128);

    const int r  = tid >> 1;
    const int hc = (tid & 1) * 16;
    const bool av = r < rows_a;
    const int asz = av ? 16 : 0;
    const uint32_t dst_ro = (uint32_t)(r * 80 + hc * 2);

    auto issue = [&](int kc, int st) {
        size_t go = (size_t)r * K + (size_t)kc * 32 + hc;
        uint32_t d = sb + st * STAGE_B + dst_ro;
        const __nv_bfloat16* pa = av ? (gAh + go) : gAh;
        const __nv_bfloat16* pl = av ? (gAl + go) : gAl;
        cpa16(d,                 pa,     asz);
        cpa16(d + 16,            pa + 8, asz);
        cpa16(d + TILE_B,        pl,     asz);
        cpa16(d + TILE_B + 16,   pl + 8, asz);
        cpa16(d + 2 * TILE_B,      gBh + go,     16);
        cpa16(d + 2 * TILE_B + 16, gBh + go + 8, 16);
        cpa16(d + 3 * TILE_B,      gBl + go,     16);
        cpa16(d + 3 * TILE_B + 16, gBl + go + 8, 16);
        cp_commit();
    };

    float c[2][8][4];
#pragma unroll
    for (int i = 0; i < 2; i++)
#pragma unroll
        for (int j = 0; j < 8; j++)
#pragma unroll
            for (int e = 0; e < 4; e++) c[i][j][e] = 0.f;

    const int nch = K / 32;
    issue(0, 0);

    const int a_r  = wm * 32 + (lane & 15);
    const int a_c8 = (lane >> 4) * 8;
    const int b_n  = wn * 64 + (lane >> 4) * 8 + (lane & 7);
    const int b_c8 = ((lane >> 3) & 1) * 8;

    for (int kc = 0; kc < nch; kc++) {
        const int st = kc & 1;
        if (kc + 1 < nch) { issue(kc + 1, st ^ 1); cp_wait<1>(); }
        else              { cp_wait<0>(); }
        __syncthreads();

        const uint32_t sa = sb + st * STAGE_B;
#pragma unroll
        for (int ks = 0; ks < 2; ks++) {
            uint32_t ah[2][4], al[2][4];
#pragma unroll
            for (int mf = 0; mf < 2; mf++) {
                uint32_t ad = sa + (uint32_t)((a_r + mf * 16) * 80 + (ks * 16 + a_c8) * 2);
                ldsm4(ah[mf], ad);
                ldsm4(al[mf], ad + TILE_B);
            }
            uint32_t bh[8][2], bl[8][2];
#pragma unroll
            for (int nf = 0; nf < 4; nf++) {
                uint32_t bd = sa + 2 * TILE_B +
                              (uint32_t)((b_n + nf * 16) * 80 + (ks * 16 + b_c8) * 2);
                uint32_t t0[4], t1[4];
                ldsm4(t0, bd);
                ldsm4(t1, bd + TILE_B);
                bh[nf * 2][0] = t0[0]; bh[nf * 2][1] = t0[1];
                bh[nf * 2 + 1][0] = t0[2]; bh[nf * 2 + 1][1] = t0[3];
                bl[nf * 2][0] = t1[0]; bl[nf * 2][1] = t1[1];
                bl[nf * 2 + 1][0] = t1[2]; bl[nf * 2 + 1][1] = t1[3];
            }
#pragma unroll
            for (int mf = 0; mf < 2; mf++)
#pragma unroll
                for (int nf = 0; nf < 8; nf++) {
                    mma_bf16(c[mf][nf], ah[mf], bh[nf]);
                    mma_bf16(c[mf][nf], ah[mf], bl[nf]);
                    mma_bf16(c[mf][nf], al[mf], bh[nf]);
                }
        }
        __syncthreads();
    }

#pragma unroll
    for (int mf = 0; mf < 2; mf++) {
#pragma unroll
        for (int nf = 0; nf < 8; nf++) {
            int row0 = mb * 128 + wm * 32 + mf * 16 + (lane >> 2);
            int col  = nb * 128 + wn * 64 + nf * 8 + (lane & 3) * 2;
            float b0 = S.bias[col], b1 = S.bias[col + 1];
            if (row0 < M) {
                float2 o0 = make_float2(c[mf][nf][0] + b0, c[mf][nf][1] + b1);
                *(float2*)(S.out + (size_t)row0 * HID + col) = o0;
            }
            int row1 = row0 + 8;
            if (row1 < M) {
                float2 o1 = make_float2(c[mf][nf][2] + b0, c[mf][nf][3] + b1);
                *(float2*)(S.out + (size_t)row1 * HID + col) = o1;
            }
        }
    }
}

// ---------------- flash attention, mma.sync bf16 hi/lo ----------------
// CTA: (qtile mb of 128 rows, head h). 8 warps x 16 q-rows. Stream 24 key tiles of 64.
#define APITCH 272                      // bytes per smem row (136 halfs)
#define AQ_H   0
#define AQ_L   34816                    // 128*272
#define AST0   69632
#define AKV_K  17408                    // 64*272
#define ASTAGE 69632                    // KH,KL,VH,VL
#define ATTN_SMEM (AST0 + 2 * ASTAGE)   // 208896

__global__ __launch_bounds__(256) void attn_mma(
    const __nv_bfloat16* __restrict__ Qh, const __nv_bfloat16* __restrict__ Ql,
    const __nv_bfloat16* __restrict__ Kh, const __nv_bfloat16* __restrict__ Kl,
    const __nv_bfloat16* __restrict__ Vh, const __nv_bfloat16* __restrict__ Vl,
    float* __restrict__ ctx)
{
    extern __shared__ char smem[];
    const uint32_t sb = smem_u32(smem);
    const int tid = threadIdx.x, w = tid >> 5, lane = tid & 31;
    const int mb = blockIdx.x, h = blockIdx.y;
    const size_t hbase = (size_t)h * S_TOT * HD;

    // load Q tile (128 x 128 halfs, hi & lo) into smem
#pragma unroll
    for (int i = 0; i < 8; i++) {
        int c = tid + i * 256;
        int row = c >> 4, ch = c & 15;
        size_t g = hbase + (size_t)(mb * 128 + row) * HD + ch * 8;
        *(uint4*)(smem + AQ_H + row * APITCH + ch * 16) = *(const uint4*)(Qh + g);
        *(uint4*)(smem + AQ_L + row * APITCH + ch * 16) = *(const uint4*)(Ql + g);
    }

    auto issueKV = [&](int t, int st) {
        uint32_t base = sb + AST0 + st * ASTAGE;
        int key0 = t * 64;
#pragma unroll
        for (int i = 0; i < 4; i++) {
            int c = tid + i * 256;
            int row = c >> 4, ch = c & 15;
            size_t g = hbase + (size_t)(key0 + row) * HD + ch * 8;
            uint32_t d = base + row * APITCH + ch * 16;
            cpa16(d,             Kh + g, 16);
            cpa16(d + AKV_K,     Kl + g, 16);
            cpa16(d + 2 * AKV_K, Vh + g, 16);
            cpa16(d + 3 * AKV_K, Vl + g, 16);
        }
        cp_commit();
    };

    float co[16][4];
#pragma unroll
    for (int i = 0; i < 16; i++)
#pragma unroll
        for (int e = 0; e < 4; e++) co[i][e] = 0.f;
    float m0 = -1e30f, m1 = -1e30f, l0 = 0.f, l1 = 0.f;

    // fragment address bases
    const uint32_t qa_ro = (uint32_t)((w * 16 + (lane & 15)) * APITCH + ((lane >> 4) * 8) * 2);
    const int b_n  = (lane >> 4) * 8 + (lane & 7);
    const int b_c8 = ((lane >> 3) & 1) * 8;
    const uint32_t vt_ro = (uint32_t)((lane & 15) * APITCH + ((lane >> 4) * 8) * 2);

    issueKV(0, 0);

    const int NT = S_TOT / 64;  // 24
    for (int t = 0; t < NT; t++) {
        const int st = t & 1;
        if (t + 1 < NT) { issueKV(t + 1, st ^ 1); cp_wait<1>(); }
        else            { cp_wait<0>(); }
        __syncthreads();

        const uint32_t kbase = sb + AST0 + st * ASTAGE;

        // ---- S = Qh@Kh^T + Qh@Kl^T + Ql@Kh^T  (16 q-rows x 64 keys per warp) ----
        float cs[8][4];
#pragma unroll
        for (int i = 0; i < 8; i++)
#pragma unroll
            for (int e = 0; e < 4; e++) cs[i][e] = 0.f;

#pragma unroll
        for (int kt = 0; kt < 8; kt++) {
            uint32_t ah[4], al[4];
            uint32_t qa = sb + qa_ro + (uint32_t)(kt * 32);   // kt*16 halfs = 32B
            ldsm4(ah, qa + AQ_H);
            ldsm4(al, qa + AQ_L);
#pragma unroll
            for (int nfp = 0; nfp < 4; nfp++) {
                uint32_t bd = kbase + (uint32_t)((b_n + nfp * 16) * APITCH + (kt * 16 + b_c8) * 2);
                uint32_t t0[4], t1[4];
                ldsm4(t0, bd);
                ldsm4(t1, bd + AKV_K);
                mma_bf16s(cs[nfp * 2],     ah, t0[0], t0[1]);
                mma_bf16s(cs[nfp * 2 + 1], ah, t0[2], t0[3]);
                mma_bf16s(cs[nfp * 2],     ah, t1[0], t1[1]);
                mma_bf16s(cs[nfp * 2 + 1], ah, t1[2], t1[3]);
                mma_bf16s(cs[nfp * 2],     al, t0[0], t0[1]);
                mma_bf16s(cs[nfp * 2 + 1], al, t0[2], t0[3]);
            }
        }

        // ---- online softmax (rows r0 = lane>>2, r1 = r0+8) ----
        float mx0 = m0, mx1 = m1;
#pragma unroll
        for (int nf = 0; nf < 8; nf++) {
            mx0 = fmaxf(mx0, fmaxf(cs[nf][0], cs[nf][1]));
            mx1 = fmaxf(mx1, fmaxf(cs[nf][2], cs[nf][3]));
        }
        mx0 = fmaxf(mx0, __shfl_xor_sync(0xffffffffu, mx0, 1));
        mx0 = fmaxf(mx0, __shfl_xor_sync(0xffffffffu, mx0, 2));
        mx1 = fmaxf(mx1, __shfl_xor_sync(0xffffffffu, mx1, 1));
        mx1 = fmaxf(mx1, __shfl_xor_sync(0xffffffffu, mx1, 2));
        float corr0 = __expf(m0 - mx0), corr1 = __expf(m1 - mx1);
        m0 = mx0; m1 = mx1;

        float rs0 = 0.f, rs1 = 0.f;
        uint32_t ph[4][4], pl[4][4];
#pragma unroll
        for (int kt = 0; kt < 4; kt++) {
#pragma unroll
            for (int hh = 0; hh < 2; hh++) {
                int nf = 2 * kt + hh;
                float p0 = __expf(cs[nf][0] - m0), p1 = __expf(cs[nf][1] - m0);
                float p2 = __expf(cs[nf][2] - m1), p3 = __expf(cs[nf][3] - m1);
                rs0 += p0 + p1; rs1 += p2 + p3;
                float h0 = __bfloat162float(__float2bfloat16(p0));
                float h1 = __bfloat162float(__float2bfloat16(p1));
                float h2 = __bfloat162float(__float2bfloat16(p2));
                float h3 = __bfloat162float(__float2bfloat16(p3));
                ph[kt][hh * 2]     = packbf(h0, h1);
                ph[kt][hh * 2 + 1] = packbf(h2, h3);
                pl[kt][hh * 2]     = packbf(p0 - h0, p1 - h1);
                pl[kt][hh * 2 + 1] = packbf(p2 - h2, p3 - h3);
            }
        }
        rs0 += __shfl_xor_sync(0xffffffffu, rs0, 1);
        rs0 += __shfl_xor_sync(0xffffffffu, rs0, 2);
        rs1 += __shfl_xor_sync(0xffffffffu, rs1, 1);
        rs1 += __shfl_xor_sync(0xffffffffu, rs1, 2);
        l0 = l0 * corr0 + rs0;
        l1 = l1 * corr1 + rs1;

#pragma unroll
        for (int nf = 0; nf < 16; nf++) {
            co[nf][0] *= corr0; co[nf][1] *= corr0;
            co[nf][2] *= corr1; co[nf][3] *= corr1;
        }

        // ---- O += Ph@Vh + Ph@Vl + Pl@Vh ----
        const uint32_t vbase = kbase + 2 * AKV_K;
#pragma unroll
        for (int kt = 0; kt < 4; kt++) {
#pragma unroll
            for (int np = 0; np < 8; np++) {
                uint32_t vd = vbase + vt_ro + (uint32_t)(kt * 16 * APITCH + np * 32);
                uint32_t th[4], tl[4];
                ldsm4t(th, vd);
                ldsm4t(tl, vd + AKV_K);
                mma_bf16s(co[np * 2],     ph[kt], th[0], th[1]);
                mma_bf16s(co[np * 2 + 1], ph[kt], th[2], th[3]);
                mma_bf16s(co[np * 2],     ph[kt], tl[0], tl[1]);
                mma_bf16s(co[np * 2 + 1], ph[kt], tl[2], tl[3]);
                mma_bf16s(co[np * 2],     pl[kt], th[0], th[1]);
                mma_bf16s(co[np * 2 + 1], pl[kt], th[2], th[3]);
            }
        }
        __syncthreads();
    }

    // ---- epilogue: ctx[q][h*128 + d] = O / l ----
    float i0 = 1.f / l0, i1 = 1.f / l1;
    int r0g = mb * 128 + w * 16 + (lane >> 2);
#pragma unroll
    for (int nf = 0; nf < 16; nf++) {
        int col = h * HD + nf * 8 + (lane & 3) * 2;
        *(float2*)(ctx + (size_t)r0g * HID + col) =
            make_float2(co[nf][0] * i0, co[nf][1] * i0);
        *(float2*)(ctx + (size_t)(r0g + 8) * HID + col) =
            make_float2(co[nf][2] * i1, co[nf][3] * i1);
    }
}

// ---------------- fp32 -> bf16 hi/lo split (elementwise) ----------------
__global__ __launch_bounds__(256) void conv_act(
    const float* __restrict__ x, __nv_bfloat16* __restrict__ h,
    __nv_bfloat16* __restrict__ l, int n4)
{
    int i = blockIdx.x * 256 + threadIdx.x;
    if (i >= n4) return;
    float4 v = ((const float4*)x)[i];
    __nv_bfloat16 h0 = __float2bfloat16(v.x), h1 = __float2bfloat16(v.y);
    __nv_bfloat16 h2 = __float2bfloat16(v.z), h3 = __float2bfloat16(v.w);
    __nv_bfloat16 l0 = __float2bfloat16(v.x - __bfloat162float(h0));
    __nv_bfloat16 l1 = __float2bfloat16(v.y - __bfloat162float(h1));
    __nv_bfloat16 l2 = __float2bfloat16(v.z - __bfloat162float(h2));
    __nv_bfloat16 l3 = __float2bfloat16(v.w - __bfloat162float(h3));
    ((__nv_bfloat162*)h)[2 * i]     = __nv_bfloat162(h0, h1);
    ((__nv_bfloat162*)h)[2 * i + 1] = __nv_bfloat162(h2, h3);
    ((__nv_bfloat162*)l)[2 * i]     = __nv_bfloat162(l0, l1);
    ((__nv_bfloat162*)l)[2 * i + 1] = __nv_bfloat162(l2, l3);
}

// ---------------- W[K][N] fp32 -> W^T[N][K] bf16 hi/lo ----------------
__global__ __launch_bounds__(256) void conv_wT(
    const float* __restrict__ W, __nv_bfloat16* __restrict__ th,
    __nv_bfloat16* __restrict__ tl, int K, int N)
{
    __shared__ float s[32][33];
    const int tx = threadIdx.x & 31, ty = threadIdx.x >> 5;
    const int k0 = blockIdx.y * 32, n0 = blockIdx.x * 32;
#pragma unroll
    for (int r = 0; r < 4; r++)
        s[ty + r * 8][tx] = W[(size_t)(k0 + ty + r * 8) * N + n0 + tx];
    __syncthreads();
#pragma unroll
    for (int r = 0; r < 4; r++) {
        int n = n0 + ty + r * 8, k = k0 + tx;
        float v = s[tx][ty + r * 8];
        __nv_bfloat16 h = __float2bfloat16(v);
        th[(size_t)n * K + k] = h;
        tl[(size_t)n * K + k] = __float2bfloat16(v - __bfloat162float(h));
    }
}

// ---------------- prepare: rms + rope + head layout -> bf16 hi/lo ----------------
__global__ __launch_bounds__(128) void prepare_qkv(
    const float* __restrict__ q,  const float* __restrict__ k,  const float* __restrict__ v,
    const float* __restrict__ eq, const float* __restrict__ ek, const float* __restrict__ ev,
    const float* __restrict__ nq, const float* __restrict__ nk,
    const float* __restrict__ naq,const float* __restrict__ nak,
    const float* __restrict__ cosr, const float* __restrict__ sinr,
    __nv_bfloat16* __restrict__ qh, __nv_bfloat16* __restrict__ ql,
    __nv_bfloat16* __restrict__ kh, __nv_bfloat16* __restrict__ kl,
    __nv_bfloat16* __restrict__ vh, __nv_bfloat16* __restrict__ vl)
{
    const int s = blockIdx.x;
    const int h = blockIdx.y;
    const int d = threadIdx.x;
    const int col = h * HD + d;

    const float *sq, *sk, *sv, *wq, *wk;
    if (s < S_TXT) {
        sq = eq + (size_t)s * HID; sk = ek + (size_t)s * HID; sv = ev + (size_t)s * HID;
        wq = naq; wk = nak;
    } else {
        int si = s - S_TXT;
        sq = q + (size_t)si * HID; sk = k + (size_t)si * HID; sv = v + (size_t)si * HID;
        wq = nq; wk = nk;
    }
    float xq = sq[col], xk = sk[col], xv = sv[col];

    __shared__ float red[8];
    float s2q = xq * xq, s2k = xk * xk;
#pragma unroll
    for (int o = 16; o; o >>= 1) {
        s2q += __shfl_xor_sync(0xffffffffu, s2q, o);
        s2k += __shfl_xor_sync(0xffffffffu, s2k, o);
    }
    int wid = d >> 5, lid = d & 31;
    if (lid == 0) { red[wid] = s2q; red[4 + wid] = s2k; }
    __syncthreads();
    float tq = red[0] + red[1] + red[2] + red[3];
    float tk = red[4] + red[5] + red[6] + red[7];
    float rq = rsqrtf(tq / (float)HD + EPS_F);
    float rk = rsqrtf(tk / (float)HD + EPS_F);
    float nxq = xq * rq * wq[d];
    float nxk = xk * rk * wk[d];

    __shared__ float shq[128], shk[128];
    shq[d] = nxq; shk[d] = nxk;
    __syncthreads();

    float c  = cosr[(size_t)s * HD + d];
    float sn = sinr[(size_t)s * HD + d];
    float oq, ok;
    if ((d & 1) == 0) {
        oq = nxq * c - shq[d + 1] * sn;
        ok = nxk * c - shk[d + 1] * sn;
    } else {
        oq = nxq * c + shq[d - 1] * sn;
        ok = nxk * c + shk[d - 1] * sn;
    }
    oq *= SM_SCALE;   // fold softmax scale into q

    size_t o = ((size_t)h * S_TOT + s) * HD + d;
    __nv_bfloat16 hq = __float2bfloat16(oq);
    __nv_bfloat16 hk = __float2bfloat16(ok);
    __nv_bfloat16 hv = __float2bfloat16(xv);
    qh[o] = hq; ql[o] = __float2bfloat16(oq - __bfloat162float(hq));
    kh[o] = hk; kl[o] = __float2bfloat16(ok - __bfloat162float(hk));
    vh[o] = hv; vl[o] = __float2bfloat16(xv - __bfloat162float(hv));
}

// ---------------- IP attention (unchanged, validated) ----------------
__global__ __launch_bounds__(256) void ip_attn(
    const float* __restrict__ q, const float* __restrict__ ipk, const float* __restrict__ ipv,
    const float* __restrict__ wqn, const float* __restrict__ wkn,
    float* __restrict__ ctx)
{
    __shared__ float sK[LIP * HD];
    __shared__ float sV[LIP * HD];
    const int t = threadIdx.x, h = blockIdx.y;
    const int w = t >> 5, lane = t & 31;

#pragma unroll
    for (int i = 0; i < 8; i++) {
        int idx = t + i * 256;
        int r = idx >> 7, c = idx & 127;
        sK[idx] = ipk[(size_t)r * HID + h * HD + c];
        sV[idx] = ipv[(size_t)r * HID + h * HD + c];
    }
    __syncthreads();

    float4 wk4 = *(const float4*)(wkn + lane * 4);
    for (int rr = w; rr < LIP; rr += 8) {
        float4 kv = ((float4*)sK)[rr * 32 + lane];
        float ss = kv.x * kv.x + kv.y * kv.y + kv.z * kv.z + kv.w * kv.w;
#pragma unroll
        for (int o = 16; o; o >>= 1) ss += __shfl_xor_sync(0xffffffffu, ss, o);
        float r = rsqrtf(ss / (float)HD + EPS_F);
        kv.x *= r * wk4.x; kv.y *= r * wk4.y; kv.z *= r * wk4.z; kv.w *= r * wk4.w;
        ((float4*)sK)[rr * 32 + lane] = kv;
    }
    __syncthreads();

    const int s = blockIdx.x * 8 + w;
    float4 q4 = *(const float4*)(q + (size_t)s * HID + h * HD + lane * 4);
    float ss = q4.x * q4.x + q4.y * q4.y + q4.z * q4.z + q4.w * q4.w;
#pragma unroll
    for (int o = 16; o; o >>= 1) ss += __shfl_xor_sync(0xffffffffu, ss, o);
    float rq = rsqrtf(ss / (float)HD + EPS_F);
    float4 wq4 = *(const float4*)(wqn + lane * 4);
    q4.x *= rq * wq4.x; q4.y *= rq * wq4.y; q4.z *= rq * wq4.z; q4.w *= rq * wq4.w;

    float sc[LIP];
#pragma unroll
    for (int j = 0; j < LIP; j++) {
        float4 kv = ((const float4*)sK)[j * 32 + lane];
        float d = q4.x * kv.x + q4.y * kv.y + q4.z * kv.z + q4.w * kv.w;
#pragma unroll
        for (int o = 16; o; o >>= 1) d += __shfl_xor_sync(0xffffffffu, d, o);
        sc[j] = d * SM_SCALE;
    }
    float mx = sc[0];
#pragma unroll
    for (int j = 1; j < LIP; j++) mx = fmaxf(mx, sc[j]);
    float l = 0.f;
#pragma unroll
    for (int j = 0; j < LIP; j++) { sc[j] = __expf(sc[j] - mx); l += sc[j]; }
    float inv = 1.f / l;

    float4 acc = make_float4(0.f, 0.f, 0.f, 0.f);
#pragma unroll
    for (int j = 0; j < LIP; j++) {
        float p = sc[j] * inv;
        float4 vv = ((const float4*)sV)[j * 32 + lane];
        acc.x += p * vv.x; acc.y += p * vv.y; acc.z += p * vv.z; acc.w += p * vv.w;
    }
    float* o = ctx + (size_t)(S_TXT + s) * HID + h * HD + lane * 4;
    float4 cur = *(float4*)o;
    cur.x += acc.x; cur.y += acc.y; cur.z += acc.z; cur.w += acc.w;
    *(float4*)o = cur;
}

// ---------------- host launch ----------------
static float* symf(const void* s) { void* p = nullptr; cudaGetSymbolAddress(&p, s); return (float*)p; }
static __nv_bfloat16* symb(const void* s) { void* p = nullptr; cudaGetSymbolAddress(&p, s); return (__nv_bfloat16*)p; }

extern "C" void kernel_launch(void* const* d_in, const int* in_sizes, int n_in,
                              void* d_out, int out_size)
{
    const float* hs    = (const float*)d_in[0];
    const float* enc   = (const float*)d_in[1];
    const float* iph   = (const float*)d_in[2];
    const float* rcos  = (const float*)d_in[3];
    const float* rsin  = (const float*)d_in[4];
    const float* Wq    = (const float*)d_in[5];
    const float* bq    = (const float*)d_in[6];
    const float* Wk    = (const float*)d_in[7];
    const float* bk    = (const float*)d_in[8];
    const float* Wv    = (const float*)d_in[9];
    const float* bv    = (const float*)d_in[10];
    const float* nqw   = (const float*)d_in[11];
    const float* nkw   = (const float*)d_in[12];
    const float* Waq   = (const float*)d_in[13];
    const float* baq   = (const float*)d_in[14];
    const float* Wak   = (const float*)d_in[15];
    const float* bak   = (const float*)d_in[16];
    const float* Wav   = (const float*)d_in[17];
    const float* bav   = (const float*)d_in[18];
    const float* naqw  = (const float*)d_in[19];
    const float* nakw  = (const float*)d_in[20];
    const float* Wo    = (const float*)d_in[21];
    const float* bo    = (const float*)d_in[22];
    const float* Wadd  = (const float*)d_in[23];
    const float* badd  = (const float*)d_in[24];
    const float* Wkip  = (const float*)d_in[25];
    const float* bkip  = (const float*)d_in[26];
    const float* Wvip  = (const float*)d_in[27];
    const float* bvip  = (const float*)d_in[28];
    const float* nipq  = (const float*)d_in[29];
    const float* nipk  = (const float*)d_in[30];

    float* out = (float*)d_out;

    float* pq   = symf(g_q);   float* pk   = symf(g_k);   float* pv   = symf(g_v);
    float* peq  = symf(g_eq);  float* pek  = symf(g_ek);  float* pev  = symf(g_ev);
    float* pipk = symf(g_ipk); float* pipv = symf(g_ipv);
    float* pctx = symf(g_ctx);

    __nv_bfloat16 *pqh = symb(g_qh), *pql = symb(g_ql);
    __nv_bfloat16 *pkh = symb(g_kh), *pkl = symb(g_kl);
    __nv_bfloat16 *pvh = symb(g_vh), *pvl = symb(g_vl);

    __nv_bfloat16 *hsh = symb(g_hs_h),  *hsl = symb(g_hs_l);
    __nv_bfloat16 *ech = symb(g_enc_h), *ecl = symb(g_enc_l);
    __nv_bfloat16 *iph_h = symb(g_iph_h), *iph_l = symb(g_iph_l);
    __nv_bfloat16 *cxh = symb(g_ctxh),  *cxl = symb(g_ctxl);
    __nv_bfloat16 *wq_h = symb(g_WqT_h),  *wq_l = symb(g_WqT_l);
    __nv_bfloat16 *wk_h = symb(g_WkT_h),  *wk_l = symb(g_WkT_l);
    __nv_bfloat16 *wv_h = symb(g_WvT_h),  *wv_l = symb(g_WvT_l);
    __nv_bfloat16 *waq_h = symb(g_WaqT_h), *waq_l = symb(g_WaqT_l);
    __nv_bfloat16 *wak_h = symb(g_WakT_h), *wak_l = symb(g_WakT_l);
    __nv_bfloat16 *wav_h = symb(g_WavT_h), *wav_l = symb(g_WavT_l);
    __nv_bfloat16 *wo_h = symb(g_WoT_h),  *wo_l = symb(g_WoT_l);
    __nv_bfloat16 *wad_h = symb(g_WadT_h), *wad_l = symb(g_WadT_l);
    __nv_bfloat16 *wki_h = symb(g_WkiT_h), *wki_l = symb(g_WkiT_l);
    __nv_bfloat16 *wvi_h = symb(g_WviT_h), *wvi_l = symb(g_WviT_l);

    cudaFuncSetAttribute(gemm_mma, cudaFuncAttributeMaxDynamicSharedMemorySize, GEMM_SMEM);
    cudaFuncSetAttribute(attn_mma, cudaFuncAttributeMaxDynamicSharedMemorySize, ATTN_SMEM);

    // -------- conversions --------
    conv_act<<<(S_IMG * HID / 4 + 255) / 256, 256>>>(hs,  hsh, hsl, S_IMG * HID / 4);
    conv_act<<<(S_TXT * HID / 4 + 255) / 256, 256>>>(enc, ech, ecl, S_TXT * HID / 4);
    conv_act<<<(LIP * IPD / 4 + 255) / 256, 256>>>(iph, iph_h, iph_l, LIP * IPD / 4);

    dim3 wg(HID / 32, HID / 32);
    conv_wT<<<wg, 256>>>(Wq,   wq_h,  wq_l,  HID, HID);
    conv_wT<<<wg, 256>>>(Wk,   wk_h,  wk_l,  HID, HID);
    conv_wT<<<wg, 256>>>(Wv,   wv_h,  wv_l,  HID, HID);
    conv_wT<<<wg, 256>>>(Waq,  waq_h, waq_l, HID, HID);
    conv_wT<<<wg, 256>>>(Wak,  wak_h, wak_l, HID, HID);
    conv_wT<<<wg, 256>>>(Wav,  wav_h, wav_l, HID, HID);
    conv_wT<<<wg, 256>>>(Wo,   wo_h,  wo_l,  HID, HID);
    conv_wT<<<wg, 256>>>(Wadd, wad_h, wad_l, HID, HID);
    dim3 wgip(HID / 32, IPD / 32);
    conv_wT<<<wgip, 256>>>(Wkip, wki_h, wki_l, IPD, HID);
    conv_wT<<<wgip, 256>>>(Wvip, wvi_h, wvi_l, IPD, HID);

    // -------- projections (mma.sync bf16x3) --------
    GemmSet sq{wq_h, wq_l, bq, pq}, sk{wk_h, wk_l, bk, pk}, sv{wv_h, wv_l, bv, pv};
    gemm_mma<<<dim3(HID / 128, S_IMG / 128, 3), 256, GEMM_SMEM>>>(hsh, hsl, sq, sk, sv, S_IMG, HID);

    GemmSet se1{waq_h, waq_l, baq, peq}, se2{wak_h, wak_l, bak, pek}, se3{wav_h, wav_l, bav, pev};
    gemm_mma<<<dim3(HID / 128, S_TXT / 128, 3), 256, GEMM_SMEM>>>(ech, ecl, se1, se2, se3, S_TXT, HID);

    GemmSet si1{wki_h, wki_l, bkip, pipk}, si2{wvi_h, wvi_l, bvip, pipv};
    gemm_mma<<<dim3(HID / 128, 1, 2), 256, GEMM_SMEM>>>(iph_h, iph_l, si1, si2, si1, LIP, IPD);

    // -------- rms + rope + head layout + bf16 split --------
    prepare_qkv<<<dim3(S_TOT, NH), 128>>>(pq, pk, pv, peq, pek, pev,
                                          nqw, nkw, naqw, nakw, rcos, rsin,
                                          pqh, pql, pkh, pkl, pvh, pvl);

    // -------- attention (tensor-core flash) --------
    attn_mma<<<dim3(S_TOT / 128, NH), 256, ATTN_SMEM>>>(pqh, pql, pkh, pkl, pvh, pvl, pctx);
    ip_attn<<<dim3(S_IMG / 8, NH), 256>>>(pq, pipk, pipv, nipq, nipk, pctx);

    // -------- output projections --------
    conv_act<<<(S_TOT * HID / 4 + 255) / 256, 256>>>(pctx, cxh, cxl, S_TOT * HID / 4);

    GemmSet so{wo_h, wo_l, bo, out};
    gemm_mma<<<dim3(HID / 128, S_IMG / 128, 1), 256, GEMM_SMEM>>>(
        cxh + (size_t)S_TXT * HID, cxl + (size_t)S_TXT * HID, so, so, so, S_IMG, HID);

    GemmSet sa{wad_h, wad_l, badd, out + (size_t)S_IMG * HID};
    gemm_mma<<<dim3(HID / 128, S_TXT / 128, 1), 256, GEMM_SMEM>>>(
        cxh, cxl, sa, sa, sa, S_TXT, HID);
}

// round 6
// speedup vs baseline: 6.3128x; 1.4568x over previous
#include <cuda_runtime.h>
#include <cuda_bf16.h>
#include <cuda_fp16.h>
#include <cstdint>

// ---------------- problem constants ----------------
#define S_IMG 1024
#define S_TXT 512
#define S_TOT 1536
#define NH    24
#define HD    128
#define HID   3072
#define IPD   2048
#define LIP   16
#define EPS_F 1e-6f
#define SM_SCALE 0.08838834764831845f  // 1/sqrt(128)

// ---------------- fp32 scratch ----------------
__device__ float g_q [S_IMG * HID];
__device__ float g_k [S_IMG * HID];
__device__ float g_v [S_IMG * HID];
__device__ float g_eq[S_TXT * HID];
__device__ float g_ek[S_TXT * HID];
__device__ float g_ev[S_TXT * HID];
__device__ float g_ipk[LIP * HID];
__device__ float g_ipv[LIP * HID];
__device__ float g_ctx[(size_t)S_TOT * HID];

// bf16 hi/lo q/k/v in [H][S][D] layout (q pre-scaled by SM_SCALE) — attention path
__device__ __align__(16) __nv_bfloat16 g_qh[(size_t)NH * S_TOT * HD], g_ql[(size_t)NH * S_TOT * HD];
__device__ __align__(16) __nv_bfloat16 g_kh[(size_t)NH * S_TOT * HD], g_kl[(size_t)NH * S_TOT * HD];
__device__ __align__(16) __nv_bfloat16 g_vh[(size_t)NH * S_TOT * HD], g_vl[(size_t)NH * S_TOT * HD];

// ---------------- fp16 split scratch (activations hi/lo, weights hi only) ----------------
__device__ __align__(16) __half g_hs_h [S_IMG * HID], g_hs_l [S_IMG * HID];
__device__ __align__(16) __half g_enc_h[S_TXT * HID], g_enc_l[S_TXT * HID];
__device__ __align__(16) __half g_iph_h[LIP * IPD],   g_iph_l[LIP * IPD];
__device__ __align__(16) __half g_ctxh [S_TOT * HID], g_ctxl [S_TOT * HID];
// transposed weights [N][K] fp16 (hi only)
__device__ __align__(16) __half g_WqT [HID * HID];
__device__ __align__(16) __half g_WkT [HID * HID];
__device__ __align__(16) __half g_WvT [HID * HID];
__device__ __align__(16) __half g_WaqT[HID * HID];
__device__ __align__(16) __half g_WakT[HID * HID];
__device__ __align__(16) __half g_WavT[HID * HID];
__device__ __align__(16) __half g_WoT [HID * HID];
__device__ __align__(16) __half g_WadT[HID * HID];
__device__ __align__(16) __half g_WkiT[HID * IPD];
__device__ __align__(16) __half g_WviT[HID * IPD];

// ---------------- low-level helpers ----------------
__device__ __forceinline__ uint32_t smem_u32(const void* p) {
    return (uint32_t)__cvta_generic_to_shared(p);
}
__device__ __forceinline__ void cpa16(uint32_t dst, const void* src, int sz) {
    asm volatile("cp.async.cg.shared.global [%0], [%1], 16, %2;"
                 :: "r"(dst), "l"(src), "r"(sz) : "memory");
}
__device__ __forceinline__ void cp_commit() {
    asm volatile("cp.async.commit_group;" ::: "memory");
}
template<int N> __device__ __forceinline__ void cp_wait() {
    asm volatile("cp.async.wait_group %0;" :: "n"(N) : "memory");
}
__device__ __forceinline__ void ldsm4(uint32_t* r, uint32_t addr) {
    asm volatile("ldmatrix.sync.aligned.m8n8.x4.shared.b16 {%0,%1,%2,%3}, [%4];"
                 : "=r"(r[0]), "=r"(r[1]), "=r"(r[2]), "=r"(r[3]) : "r"(addr));
}
__device__ __forceinline__ void ldsm4t(uint32_t* r, uint32_t addr) {
    asm volatile("ldmatrix.sync.aligned.m8n8.x4.trans.shared.b16 {%0,%1,%2,%3}, [%4];"
                 : "=r"(r[0]), "=r"(r[1]), "=r"(r[2]), "=r"(r[3]) : "r"(addr));
}
__device__ __forceinline__ void mma_f16(float* c, const uint32_t* a, uint32_t b0, uint32_t b1) {
    asm volatile(
        "mma.sync.aligned.m16n8k16.row.col.f32.f16.f16.f32 "
        "{%0,%1,%2,%3}, {%4,%5,%6,%7}, {%8,%9}, {%0,%1,%2,%3};"
        : "+f"(c[0]), "+f"(c[1]), "+f"(c[2]), "+f"(c[3])
        : "r"(a[0]), "r"(a[1]), "r"(a[2]), "r"(a[3]), "r"(b0), "r"(b1));
}
__device__ __forceinline__ void mma_bf16s(float* c, const uint32_t* a, uint32_t b0, uint32_t b1) {
    asm volatile(
        "mma.sync.aligned.m16n8k16.row.col.f32.bf16.bf16.f32 "
        "{%0,%1,%2,%3}, {%4,%5,%6,%7}, {%8,%9}, {%0,%1,%2,%3};"
        : "+f"(c[0]), "+f"(c[1]), "+f"(c[2]), "+f"(c[3])
        : "r"(a[0]), "r"(a[1]), "r"(a[2]), "r"(a[3]), "r"(b0), "r"(b1));
}
__device__ __forceinline__ uint32_t packbf(float a, float b) {
    __nv_bfloat162 t = __floats2bfloat162_rn(a, b);
    return *(uint32_t*)&t;
}

struct GemmSet { const __half* bh; const float* bias; float* out; };

// ---------------- mma.sync fp16 2-term GEMM ----------------
// C = (Ah + Al) @ Wh^T + bias.  128x128 CTA tile, BK=32, 8 warps.
// Smem tiles: AH, AL, BH; [128 rows][40 halfs] (80B pitch, conflict-free ldmatrix).
#define TILE_B  10240                 // 128*40*2
#define STAGE_B (3 * TILE_B)          // AH, AL, BH
#define GEMM_SMEM (2 * STAGE_B)       // 61440, double buffered

__global__ __launch_bounds__(256) void gemm_mma(
    const __half* __restrict__ Ahi, const __half* __restrict__ Alo,
    GemmSet s0, GemmSet s1, GemmSet s2, int M, int K)
{
    extern __shared__ char smem[];
    const uint32_t sb = smem_u32(smem);
    const int tid = threadIdx.x, warp = tid >> 5, lane = tid & 31;
    const GemmSet S = (blockIdx.z == 0) ? s0 : ((blockIdx.z == 1) ? s1 : s2);
    const int nb = blockIdx.x, mb = blockIdx.y;
    const int wm = warp & 3, wn = warp >> 2;

    const __half* gAh = Ahi  + (size_t)mb * 128 * K;
    const __half* gAl = Alo  + (size_t)mb * 128 * K;
    const __half* gBh = S.bh + (size_t)nb * 128 * K;
    const int rows_a = min(128, M - mb * 128);

    const int r  = tid >> 1;
    const int hc = (tid & 1) * 16;
    const bool av = r < rows_a;
    const int asz = av ? 16 : 0;
    const uint32_t dst_ro = (uint32_t)(r * 80 + hc * 2);

    auto issue = [&](int kc, int st) {
        size_t go = (size_t)r * K + (size_t)kc * 32 + hc;
        uint32_t d = sb + st * STAGE_B + dst_ro;
        const __half* pa = av ? (gAh + go) : gAh;
        const __half* pl = av ? (gAl + go) : gAl;
        cpa16(d,                   pa,     asz);
        cpa16(d + 16,              pa + 8, asz);
        cpa16(d + TILE_B,          pl,     asz);
        cpa16(d + TILE_B + 16,     pl + 8, asz);
        cpa16(d + 2 * TILE_B,      gBh + go,     16);
        cpa16(d + 2 * TILE_B + 16, gBh + go + 8, 16);
        cp_commit();
    };

    float c[2][8][4];
#pragma unroll
    for (int i = 0; i < 2; i++)
#pragma unroll
        for (int j = 0; j < 8; j++)
#pragma unroll
            for (int e = 0; e < 4; e++) c[i][j][e] = 0.f;

    const int nch = K / 32;
    issue(0, 0);

    const int a_r  = wm * 32 + (lane & 15);
    const int a_c8 = (lane >> 4) * 8;
    const int b_n  = wn * 64 + (lane >> 4) * 8 + (lane & 7);
    const int b_c8 = ((lane >> 3) & 1) * 8;

    for (int kc = 0; kc < nch; kc++) {
        const int st = kc & 1;
        if (kc + 1 < nch) { issue(kc + 1, st ^ 1); cp_wait<1>(); }
        else              { cp_wait<0>(); }
        __syncthreads();

        const uint32_t sa = sb + st * STAGE_B;
#pragma unroll
        for (int ks = 0; ks < 2; ks++) {
            uint32_t ah[2][4], al[2][4];
#pragma unroll
            for (int mf = 0; mf < 2; mf++) {
                uint32_t ad = sa + (uint32_t)((a_r + mf * 16) * 80 + (ks * 16 + a_c8) * 2);
                ldsm4(ah[mf], ad);
                ldsm4(al[mf], ad + TILE_B);
            }
            uint32_t bh[8][2];
#pragma unroll
            for (int nf = 0; nf < 4; nf++) {
                uint32_t bd = sa + 2 * TILE_B +
                              (uint32_t)((b_n + nf * 16) * 80 + (ks * 16 + b_c8) * 2);
                uint32_t t0[4];
                ldsm4(t0, bd);
                bh[nf * 2][0] = t0[0]; bh[nf * 2][1] = t0[1];
                bh[nf * 2 + 1][0] = t0[2]; bh[nf * 2 + 1][1] = t0[3];
            }
#pragma unroll
            for (int mf = 0; mf < 2; mf++)
#pragma unroll
                for (int nf = 0; nf < 8; nf++) {
                    mma_f16(c[mf][nf], ah[mf], bh[nf][0], bh[nf][1]);
                    mma_f16(c[mf][nf], al[mf], bh[nf][0], bh[nf][1]);
                }
        }
        __syncthreads();
    }

#pragma unroll
    for (int mf = 0; mf < 2; mf++) {
#pragma unroll
        for (int nf = 0; nf < 8; nf++) {
            int row0 = mb * 128 + wm * 32 + mf * 16 + (lane >> 2);
            int col  = nb * 128 + wn * 64 + nf * 8 + (lane & 3) * 2;
            float b0 = S.bias[col], b1 = S.bias[col + 1];
            if (row0 < M) {
                float2 o0 = make_float2(c[mf][nf][0] + b0, c[mf][nf][1] + b1);
                *(float2*)(S.out + (size_t)row0 * HID + col) = o0;
            }
            int row1 = row0 + 8;
            if (row1 < M) {
                float2 o1 = make_float2(c[mf][nf][2] + b0, c[mf][nf][3] + b1);
                *(float2*)(S.out + (size_t)row1 * HID + col) = o1;
            }
        }
    }
}

// ---------------- flash attention, mma.sync bf16 hi/lo (validated R5, unchanged) ----------------
#define APITCH 272
#define AQ_H   0
#define AQ_L   34816
#define AST0   69632
#define AKV_K  17408
#define ASTAGE 69632
#define ATTN_SMEM (AST0 + 2 * ASTAGE)

__global__ __launch_bounds__(256) void attn_mma(
    const __nv_bfloat16* __restrict__ Qh, const __nv_bfloat16* __restrict__ Ql,
    const __nv_bfloat16* __restrict__ Kh, const __nv_bfloat16* __restrict__ Kl,
    const __nv_bfloat16* __restrict__ Vh, const __nv_bfloat16* __restrict__ Vl,
    float* __restrict__ ctx)
{
    extern __shared__ char smem[];
    const uint32_t sb = smem_u32(smem);
    const int tid = threadIdx.x, w = tid >> 5, lane = tid & 31;
    const int mb = blockIdx.x, h = blockIdx.y;
    const size_t hbase = (size_t)h * S_TOT * HD;

#pragma unroll
    for (int i = 0; i < 8; i++) {
        int c = tid + i * 256;
        int row = c >> 4, ch = c & 15;
        size_t g = hbase + (size_t)(mb * 128 + row) * HD + ch * 8;
        *(uint4*)(smem + AQ_H + row * APITCH + ch * 16) = *(const uint4*)(Qh + g);
        *(uint4*)(smem + AQ_L + row * APITCH + ch * 16) = *(const uint4*)(Ql + g);
    }

    auto issueKV = [&](int t, int st) {
        uint32_t base = sb + AST0 + st * ASTAGE;
        int key0 = t * 64;
#pragma unroll
        for (int i = 0; i < 4; i++) {
            int c = tid + i * 256;
            int row = c >> 4, ch = c & 15;
            size_t g = hbase + (size_t)(key0 + row) * HD + ch * 8;
            uint32_t d = base + row * APITCH + ch * 16;
            cpa16(d,             Kh + g, 16);
            cpa16(d + AKV_K,     Kl + g, 16);
            cpa16(d + 2 * AKV_K, Vh + g, 16);
            cpa16(d + 3 * AKV_K, Vl + g, 16);
        }
        cp_commit();
    };

    float co[16][4];
#pragma unroll
    for (int i = 0; i < 16; i++)
#pragma unroll
        for (int e = 0; e < 4; e++) co[i][e] = 0.f;
    float m0 = -1e30f, m1 = -1e30f, l0 = 0.f, l1 = 0.f;

    const uint32_t qa_ro = (uint32_t)((w * 16 + (lane & 15)) * APITCH + ((lane >> 4) * 8) * 2);
    const int b_n  = (lane >> 4) * 8 + (lane & 7);
    const int b_c8 = ((lane >> 3) & 1) * 8;
    const uint32_t vt_ro = (uint32_t)((lane & 15) * APITCH + ((lane >> 4) * 8) * 2);

    issueKV(0, 0);

    const int NT = S_TOT / 64;
    for (int t = 0; t < NT; t++) {
        const int st = t & 1;
        if (t + 1 < NT) { issueKV(t + 1, st ^ 1); cp_wait<1>(); }
        else            { cp_wait<0>(); }
        __syncthreads();

        const uint32_t kbase = sb + AST0 + st * ASTAGE;

        float cs[8][4];
#pragma unroll
        for (int i = 0; i < 8; i++)
#pragma unroll
            for (int e = 0; e < 4; e++) cs[i][e] = 0.f;

#pragma unroll
        for (int kt = 0; kt < 8; kt++) {
            uint32_t ah[4], al[4];
            uint32_t qa = sb + qa_ro + (uint32_t)(kt * 32);
            ldsm4(ah, qa + AQ_H);
            ldsm4(al, qa + AQ_L);
#pragma unroll
            for (int nfp = 0; nfp < 4; nfp++) {
                uint32_t bd = kbase + (uint32_t)((b_n + nfp * 16) * APITCH + (kt * 16 + b_c8) * 2);
                uint32_t t0[4], t1[4];
                ldsm4(t0, bd);
                ldsm4(t1, bd + AKV_K);
                mma_bf16s(cs[nfp * 2],     ah, t0[0], t0[1]);
                mma_bf16s(cs[nfp * 2 + 1], ah, t0[2], t0[3]);
                mma_bf16s(cs[nfp * 2],     ah, t1[0], t1[1]);
                mma_bf16s(cs[nfp * 2 + 1], ah, t1[2], t1[3]);
                mma_bf16s(cs[nfp * 2],     al, t0[0], t0[1]);
                mma_bf16s(cs[nfp * 2 + 1], al, t0[2], t0[3]);
            }
        }

        float mx0 = m0, mx1 = m1;
#pragma unroll
        for (int nf = 0; nf < 8; nf++) {
            mx0 = fmaxf(mx0, fmaxf(cs[nf][0], cs[nf][1]));
            mx1 = fmaxf(mx1, fmaxf(cs[nf][2], cs[nf][3]));
        }
        mx0 = fmaxf(mx0, __shfl_xor_sync(0xffffffffu, mx0, 1));
        mx0 = fmaxf(mx0, __shfl_xor_sync(0xffffffffu, mx0, 2));
        mx1 = fmaxf(mx1, __shfl_xor_sync(0xffffffffu, mx1, 1));
        mx1 = fmaxf(mx1, __shfl_xor_sync(0xffffffffu, mx1, 2));
        float corr0 = __expf(m0 - mx0), corr1 = __expf(m1 - mx1);
        m0 = mx0; m1 = mx1;

        float rs0 = 0.f, rs1 = 0.f;
        uint32_t ph[4][4], pl[4][4];
#pragma unroll
        for (int kt = 0; kt < 4; kt++) {
#pragma unroll
            for (int hh = 0; hh < 2; hh++) {
                int nf = 2 * kt + hh;
                float p0 = __expf(cs[nf][0] - m0), p1 = __expf(cs[nf][1] - m0);
                float p2 = __expf(cs[nf][2] - m1), p3 = __expf(cs[nf][3] - m1);
                rs0 += p0 + p1; rs1 += p2 + p3;
                float h0 = __bfloat162float(__float2bfloat16(p0));
                float h1 = __bfloat162float(__float2bfloat16(p1));
                float h2 = __bfloat162float(__float2bfloat16(p2));
                float h3 = __bfloat162float(__float2bfloat16(p3));
                ph[kt][hh * 2]     = packbf(h0, h1);
                ph[kt][hh * 2 + 1] = packbf(h2, h3);
                pl[kt][hh * 2]     = packbf(p0 - h0, p1 - h1);
                pl[kt][hh * 2 + 1] = packbf(p2 - h2, p3 - h3);
            }
        }
        rs0 += __shfl_xor_sync(0xffffffffu, rs0, 1);
        rs0 += __shfl_xor_sync(0xffffffffu, rs0, 2);
        rs1 += __shfl_xor_sync(0xffffffffu, rs1, 1);
        rs1 += __shfl_xor_sync(0xffffffffu, rs1, 2);
        l0 = l0 * corr0 + rs0;
        l1 = l1 * corr1 + rs1;

#pragma unroll
        for (int nf = 0; nf < 16; nf++) {
            co[nf][0] *= corr0; co[nf][1] *= corr0;
            co[nf][2] *= corr1; co[nf][3] *= corr1;
        }

        const uint32_t vbase = kbase + 2 * AKV_K;
#pragma unroll
        for (int kt = 0; kt < 4; kt++) {
#pragma unroll
            for (int np = 0; np < 8; np++) {
                uint32_t vd = vbase + vt_ro + (uint32_t)(kt * 16 * APITCH + np * 32);
                uint32_t th[4], tl[4];
                ldsm4t(th, vd);
                ldsm4t(tl, vd + AKV_K);
                mma_bf16s(co[np * 2],     ph[kt], th[0], th[1]);
                mma_bf16s(co[np * 2 + 1], ph[kt], th[2], th[3]);
                mma_bf16s(co[np * 2],     ph[kt], tl[0], tl[1]);
                mma_bf16s(co[np * 2 + 1], ph[kt], tl[2], tl[3]);
                mma_bf16s(co[np * 2],     pl[kt], th[0], th[1]);
                mma_bf16s(co[np * 2 + 1], pl[kt], th[2], th[3]);
            }
        }
        __syncthreads();
    }

    float i0 = 1.f / l0, i1 = 1.f / l1;
    int r0g = mb * 128 + w * 16 + (lane >> 2);
#pragma unroll
    for (int nf = 0; nf < 16; nf++) {
        int col = h * HD + nf * 8 + (lane & 3) * 2;
        *(float2*)(ctx + (size_t)r0g * HID + col) =
            make_float2(co[nf][0] * i0, co[nf][1] * i0);
        *(float2*)(ctx + (size_t)(r0g + 8) * HID + col) =
            make_float2(co[nf][2] * i1, co[nf][3] * i1);
    }
}

// ---------------- fp32 -> fp16 hi/lo split (elementwise) ----------------
__global__ __launch_bounds__(256) void conv_act(
    const float* __restrict__ x, __half* __restrict__ h,
    __half* __restrict__ l, int n4)
{
    int i = blockIdx.x * 256 + threadIdx.x;
    if (i >= n4) return;
    float4 v = ((const float4*)x)[i];
    __half h0 = __float2half_rn(v.x), h1 = __float2half_rn(v.y);
    __half h2 = __float2half_rn(v.z), h3 = __float2half_rn(v.w);
    __half l0 = __float2half_rn(v.x - __half2float(h0));
    __half l1 = __float2half_rn(v.y - __half2float(h1));
    __half l2 = __float2half_rn(v.z - __half2float(h2));
    __half l3 = __float2half_rn(v.w - __half2float(h3));
    ((__half2*)h)[2 * i]     = __half2(h0, h1);
    ((__half2*)h)[2 * i + 1] = __half2(h2, h3);
    ((__half2*)l)[2 * i]     = __half2(l0, l1);
    ((__half2*)l)[2 * i + 1] = __half2(l2, l3);
}

// ---------------- W[K][N] fp32 -> W^T[N][K] fp16 (hi only), batched by z ----------------
struct WTask { const float* W; __half* T; };

__global__ __launch_bounds__(256) void conv_wT(
    WTask t0, WTask t1, WTask t2, int K, int N)
{
    __shared__ float s[32][33];
    const WTask T = (blockIdx.z == 0) ? t0 : ((blockIdx.z == 1) ? t1 : t2);
    const int tx = threadIdx.x & 31, ty = threadIdx.x >> 5;
    const int k0 = blockIdx.y * 32, n0 = blockIdx.x * 32;
#pragma unroll
    for (int r = 0; r < 4; r++)
        s[ty + r * 8][tx] = T.W[(size_t)(k0 + ty + r * 8) * N + n0 + tx];
    __syncthreads();
#pragma unroll
    for (int r = 0; r < 4; r++) {
        int n = n0 + ty + r * 8, k = k0 + tx;
        T.T[(size_t)n * K + k] = __float2half_rn(s[tx][ty + r * 8]);
    }
}

// ---------------- prepare: rms + rope + head layout -> bf16 hi/lo ----------------
__global__ __launch_bounds__(128) void prepare_qkv(
    const float* __restrict__ q,  const float* __restrict__ k,  const float* __restrict__ v,
    const float* __restrict__ eq, const float* __restrict__ ek, const float* __restrict__ ev,
    const float* __restrict__ nq, const float* __restrict__ nk,
    const float* __restrict__ naq,const float* __restrict__ nak,
    const float* __restrict__ cosr, const float* __restrict__ sinr,
    __nv_bfloat16* __restrict__ qh, __nv_bfloat16* __restrict__ ql,
    __nv_bfloat16* __restrict__ kh, __nv_bfloat16* __restrict__ kl,
    __nv_bfloat16* __restrict__ vh, __nv_bfloat16* __restrict__ vl)
{
    const int s = blockIdx.x;
    const int h = blockIdx.y;
    const int d = threadIdx.x;
    const int col = h * HD + d;

    const float *sq, *sk, *sv, *wq, *wk;
    if (s < S_TXT) {
        sq = eq + (size_t)s * HID; sk = ek + (size_t)s * HID; sv = ev + (size_t)s * HID;
        wq = naq; wk = nak;
    } else {
        int si = s - S_TXT;
        sq = q + (size_t)si * HID; sk = k + (size_t)si * HID; sv = v + (size_t)si * HID;
        wq = nq; wk = nk;
    }
    float xq = sq[col], xk = sk[col], xv = sv[col];

    __shared__ float red[8];
    float s2q = xq * xq, s2k = xk * xk;
#pragma unroll
    for (int o = 16; o; o >>= 1) {
        s2q += __shfl_xor_sync(0xffffffffu, s2q, o);
        s2k += __shfl_xor_sync(0xffffffffu, s2k, o);
    }
    int wid = d >> 5, lid = d & 31;
    if (lid == 0) { red[wid] = s2q; red[4 + wid] = s2k; }
    __syncthreads();
    float tq = red[0] + red[1] + red[2] + red[3];
    float tk = red[4] + red[5] + red[6] + red[7];
    float rq = rsqrtf(tq / (float)HD + EPS_F);
    float rk = rsqrtf(tk / (float)HD + EPS_F);
    float nxq = xq * rq * wq[d];
    float nxk = xk * rk * wk[d];

    __shared__ float shq[128], shk[128];
    shq[d] = nxq; shk[d] = nxk;
    __syncthreads();

    float c  = cosr[(size_t)s * HD + d];
    float sn = sinr[(size_t)s * HD + d];
    float oq, ok;
    if ((d & 1) == 0) {
        oq = nxq * c - shq[d + 1] * sn;
        ok = nxk * c - shk[d + 1] * sn;
    } else {
        oq = nxq * c + shq[d - 1] * sn;
        ok = nxk * c + shk[d - 1] * sn;
    }
    oq *= SM_SCALE;

    size_t o = ((size_t)h * S_TOT + s) * HD + d;
    __nv_bfloat16 hq = __float2bfloat16(oq);
    __nv_bfloat16 hk = __float2bfloat16(ok);
    __nv_bfloat16 hv = __float2bfloat16(xv);
    qh[o] = hq; ql[o] = __float2bfloat16(oq - __bfloat162float(hq));
    kh[o] = hk; kl[o] = __float2bfloat16(ok - __bfloat162float(hk));
    vh[o] = hv; vl[o] = __float2bfloat16(xv - __bfloat162float(hv));
}

// ---------------- IP attention (unchanged, validated) ----------------
__global__ __launch_bounds__(256) void ip_attn(
    const float* __restrict__ q, const float* __restrict__ ipk, const float* __restrict__ ipv,
    const float* __restrict__ wqn, const float* __restrict__ wkn,
    float* __restrict__ ctx)
{
    __shared__ float sK[LIP * HD];
    __shared__ float sV[LIP * HD];
    const int t = threadIdx.x, h = blockIdx.y;
    const int w = t >> 5, lane = t & 31;

#pragma unroll
    for (int i = 0; i < 8; i++) {
        int idx = t + i * 256;
        int r = idx >> 7, c = idx & 127;
        sK[idx] = ipk[(size_t)r * HID + h * HD + c];
        sV[idx] = ipv[(size_t)r * HID + h * HD + c];
    }
    __syncthreads();

    float4 wk4 = *(const float4*)(wkn + lane * 4);
    for (int rr = w; rr < LIP; rr += 8) {
        float4 kv = ((float4*)sK)[rr * 32 + lane];
        float ss = kv.x * kv.x + kv.y * kv.y + kv.z * kv.z + kv.w * kv.w;
#pragma unroll
        for (int o = 16; o; o >>= 1) ss += __shfl_xor_sync(0xffffffffu, ss, o);
        float r = rsqrtf(ss / (float)HD + EPS_F);
        kv.x *= r * wk4.x; kv.y *= r * wk4.y; kv.z *= r * wk4.z; kv.w *= r * wk4.w;
        ((float4*)sK)[rr * 32 + lane] = kv;
    }
    __syncthreads();

    const int s = blockIdx.x * 8 + w;
    float4 q4 = *(const float4*)(q + (size_t)s * HID + h * HD + lane * 4);
    float ss = q4.x * q4.x + q4.y * q4.y + q4.z * q4.z + q4.w * q4.w;
#pragma unroll
    for (int o = 16; o; o >>= 1) ss += __shfl_xor_sync(0xffffffffu, ss, o);
    float rq = rsqrtf(ss / (float)HD + EPS_F);
    float4 wq4 = *(const float4*)(wqn + lane * 4);
    q4.x *= rq * wq4.x; q4.y *= rq * wq4.y; q4.z *= rq * wq4.z; q4.w *= rq * wq4.w;

    float sc[LIP];
#pragma unroll
    for (int j = 0; j < LIP; j++) {
        float4 kv = ((const float4*)sK)[j * 32 + lane];
        float d = q4.x * kv.x + q4.y * kv.y + q4.z * kv.z + q4.w * kv.w;
#pragma unroll
        for (int o = 16; o; o >>= 1) d += __shfl_xor_sync(0xffffffffu, d, o);
        sc[j] = d * SM_SCALE;
    }
    float mx = sc[0];
#pragma unroll
    for (int j = 1; j < LIP; j++) mx = fmaxf(mx, sc[j]);
    float l = 0.f;
#pragma unroll
    for (int j = 0; j < LIP; j++) { sc[j] = __expf(sc[j] - mx); l += sc[j]; }
    float inv = 1.f / l;

    float4 acc = make_float4(0.f, 0.f, 0.f, 0.f);
#pragma unroll
    for (int j = 0; j < LIP; j++) {
        float p = sc[j] * inv;
        float4 vv = ((const float4*)sV)[j * 32 + lane];
        acc.x += p * vv.x; acc.y += p * vv.y; acc.z += p * vv.z; acc.w += p * vv.w;
    }
    float* o = ctx + (size_t)(S_TXT + s) * HID + h * HD + lane * 4;
    float4 cur = *(float4*)o;
    cur.x += acc.x; cur.y += acc.y; cur.z += acc.z; cur.w += acc.w;
    *(float4*)o = cur;
}

// ---------------- host launch ----------------
static float* symf(const void* s) { void* p = nullptr; cudaGetSymbolAddress(&p, s); return (float*)p; }
static __nv_bfloat16* symb(const void* s) { void* p = nullptr; cudaGetSymbolAddress(&p, s); return (__nv_bfloat16*)p; }
static __half* symh(const void* s) { void* p = nullptr; cudaGetSymbolAddress(&p, s); return (__half*)p; }

extern "C" void kernel_launch(void* const* d_in, const int* in_sizes, int n_in,
                              void* d_out, int out_size)
{
    const float* hs    = (const float*)d_in[0];
    const float* enc   = (const float*)d_in[1];
    const float* iph   = (const float*)d_in[2];
    const float* rcos  = (const float*)d_in[3];
    const float* rsin  = (const float*)d_in[4];
    const float* Wq    = (const float*)d_in[5];
    const float* bq    = (const float*)d_in[6];
    const float* Wk    = (const float*)d_in[7];
    const float* bk    = (const float*)d_in[8];
    const float* Wv    = (const float*)d_in[9];
    const float* bv    = (const float*)d_in[10];
    const float* nqw   = (const float*)d_in[11];
    const float* nkw   = (const float*)d_in[12];
    const float* Waq   = (const float*)d_in[13];
    const float* baq   = (const float*)d_in[14];
    const float* Wak   = (const float*)d_in[15];
    const float* bak   = (const float*)d_in[16];
    const float* Wav   = (const float*)d_in[17];
    const float* bav   = (const float*)d_in[18];
    const float* naqw  = (const float*)d_in[19];
    const float* nakw  = (const float*)d_in[20];
    const float* Wo    = (const float*)d_in[21];
    const float* bo    = (const float*)d_in[22];
    const float* Wadd  = (const float*)d_in[23];
    const float* badd  = (const float*)d_in[24];
    const float* Wkip  = (const float*)d_in[25];
    const float* bkip  = (const float*)d_in[26];
    const float* Wvip  = (const float*)d_in[27];
    const float* bvip  = (const float*)d_in[28];
    const float* nipq  = (const float*)d_in[29];
    const float* nipk  = (const float*)d_in[30];

    float* out = (float*)d_out;

    float* pq   = symf(g_q);   float* pk   = symf(g_k);   float* pv   = symf(g_v);
    float* peq  = symf(g_eq);  float* pek  = symf(g_ek);  float* pev  = symf(g_ev);
    float* pipk = symf(g_ipk); float* pipv = symf(g_ipv);
    float* pctx = symf(g_ctx);

    __nv_bfloat16 *pqh = symb(g_qh), *pql = symb(g_ql);
    __nv_bfloat16 *pkh = symb(g_kh), *pkl = symb(g_kl);
    __nv_bfloat16 *pvh = symb(g_vh), *pvl = symb(g_vl);

    __half *hsh = symh(g_hs_h),  *hsl = symh(g_hs_l);
    __half *ech = symh(g_enc_h), *ecl = symh(g_enc_l);
    __half *iph_h = symh(g_iph_h), *iph_l = symh(g_iph_l);
    __half *cxh = symh(g_ctxh),  *cxl = symh(g_ctxl);
    __half *wqT = symh(g_WqT),  *wkT = symh(g_WkT),  *wvT = symh(g_WvT);
    __half *waqT = symh(g_WaqT), *wakT = symh(g_WakT), *wavT = symh(g_WavT);
    __half *woT = symh(g_WoT),  *wadT = symh(g_WadT);
    __half *wkiT = symh(g_WkiT), *wviT = symh(g_WviT);

    cudaFuncSetAttribute(gemm_mma, cudaFuncAttributeMaxDynamicSharedMemorySize, GEMM_SMEM);
    cudaFuncSetAttribute(attn_mma, cudaFuncAttributeMaxDynamicSharedMemorySize, ATTN_SMEM);

    dim3 wg(HID / 32, HID / 32, 3);
    dim3 wg2(HID / 32, HID / 32, 2);
    dim3 wgip(HID / 32, IPD / 32, 2);

    // L0
    conv_act<<<(S_IMG * HID / 4 + 255) / 256, 256>>>(hs,  hsh, hsl, S_IMG * HID / 4);
    // L1
    conv_wT<<<wg, 256>>>(WTask{Wq, wqT}, WTask{Wk, wkT}, WTask{Wv, wvT}, HID, HID);
    // L2
    conv_act<<<(S_TXT * HID / 4 + 255) / 256, 256>>>(enc, ech, ecl, S_TXT * HID / 4);
    // L3
    conv_wT<<<wg, 256>>>(WTask{Waq, waqT}, WTask{Wak, wakT}, WTask{Wav, wavT}, HID, HID);
    // L4
    conv_act<<<(LIP * IPD / 4 + 255) / 256, 256>>>(iph, iph_h, iph_l, LIP * IPD / 4);

    // L5 — the big projection GEMM (profiled by ncu -s 5 -c 1)
    GemmSet sq{wqT, bq, pq}, sk{wkT, bk, pk}, sv{wvT, bv, pv};
    gemm_mma<<<dim3(HID / 128, S_IMG / 128, 3), 256, GEMM_SMEM>>>(hsh, hsl, sq, sk, sv, S_IMG, HID);

    // L6
    conv_wT<<<wgip, 256>>>(WTask{Wkip, wkiT}, WTask{Wvip, wviT}, WTask{Wkip, wkiT}, IPD, HID);
    // L7
    GemmSet se1{waqT, baq, peq}, se2{wakT, bak, pek}, se3{wavT, bav, pev};
    gemm_mma<<<dim3(HID / 128, S_TXT / 128, 3), 256, GEMM_SMEM>>>(ech, ecl, se1, se2, se3, S_TXT, HID);
    // L8
    GemmSet si1{wkiT, bkip, pipk}, si2{wviT, bvip, pipv};
    gemm_mma<<<dim3(HID / 128, 1, 2), 256, GEMM_SMEM>>>(iph_h, iph_l, si1, si2, si1, LIP, IPD);
    // L9
    conv_wT<<<wg2, 256>>>(WTask{Wo, woT}, WTask{Wadd, wadT}, WTask{Wo, woT}, HID, HID);

    // L10
    prepare_qkv<<<dim3(S_TOT, NH), 128>>>(pq, pk, pv, peq, pek, pev,
                                          nqw, nkw, naqw, nakw, rcos, rsin,
                                          pqh, pql, pkh, pkl, pvh, pvl);
    // L11
    attn_mma<<<dim3(S_TOT / 128, NH), 256, ATTN_SMEM>>>(pqh, pql, pkh, pkl, pvh, pvl, pctx);
    // L12
    ip_attn<<<dim3(S_IMG / 8, NH), 256>>>(pq, pipk, pipv, nipq, nipk, pctx);

    // L13
    conv_act<<<(S_TOT * HID / 4 + 255) / 256, 256>>>(pctx, cxh, cxl, S_TOT * HID / 4);
    // L14
    GemmSet so{woT, bo, out};
    gemm_mma<<<dim3(HID / 128, S_IMG / 128, 1), 256, GEMM_SMEM>>>(
        cxh + (size_t)S_TXT * HID, cxl + (size_t)S_TXT * HID, so, so, so, S_IMG, HID);
    // L15
    GemmSet sa{wadT, badd, out + (size_t)S_IMG * HID};
    gemm_mma<<<dim3(HID / 128, S_TXT / 128, 1), 256, GEMM_SMEM>>>(
        cxh, cxl, sa, sa, sa, S_TXT, HID);
}

// round 7
// speedup vs baseline: 7.7694x; 1.2307x over previous
#include <cuda_runtime.h>
#include <cuda_bf16.h>
#include <cuda_fp16.h>
#include <cstdint>

// ---------------- problem constants ----------------
#define S_IMG 1024
#define S_TXT 512
#define S_TOT 1536
#define NH    24
#define HD    128
#define HID   3072
#define IPD   2048
#define LIP   16
#define EPS_F 1e-6f
#define SM_SCALE 0.08838834764831845f  // 1/sqrt(128)

// ---------------- fp32 scratch ----------------
__device__ float g_q [S_IMG * HID];
__device__ float g_k [S_IMG * HID];
__device__ float g_v [S_IMG * HID];
__device__ float g_eq[S_TXT * HID];
__device__ float g_ek[S_TXT * HID];
__device__ float g_ev[S_TXT * HID];
__device__ float g_ipk[LIP * HID];
__device__ float g_ipv[LIP * HID];
__device__ float g_ctx[(size_t)S_TOT * HID];

// fp16 q (hi/lo, pre-scaled) + k/v (single) in [H][S][D] — attention path
__device__ __align__(16) __half g_aqh[(size_t)NH * S_TOT * HD], g_aql[(size_t)NH * S_TOT * HD];
__device__ __align__(16) __half g_akh[(size_t)NH * S_TOT * HD];
__device__ __align__(16) __half g_avh[(size_t)NH * S_TOT * HD];

// ---------------- fp16 split scratch (activations hi/lo, weights hi only) ----------------
__device__ __align__(16) __half g_hs_h [S_IMG * HID], g_hs_l [S_IMG * HID];
__device__ __align__(16) __half g_enc_h[S_TXT * HID], g_enc_l[S_TXT * HID];
__device__ __align__(16) __half g_iph_h[LIP * IPD],   g_iph_l[LIP * IPD];
__device__ __align__(16) __half g_ctxh [S_TOT * HID], g_ctxl [S_TOT * HID];
// transposed weights [N][K] fp16 (hi only)
__device__ __align__(16) __half g_WqT [HID * HID];
__device__ __align__(16) __half g_WkT [HID * HID];
__device__ __align__(16) __half g_WvT [HID * HID];
__device__ __align__(16) __half g_WaqT[HID * HID];
__device__ __align__(16) __half g_WakT[HID * HID];
__device__ __align__(16) __half g_WavT[HID * HID];
__device__ __align__(16) __half g_WoT [HID * HID];
__device__ __align__(16) __half g_WadT[HID * HID];
__device__ __align__(16) __half g_WkiT[HID * IPD];
__device__ __align__(16) __half g_WviT[HID * IPD];

// ---------------- low-level helpers ----------------
__device__ __forceinline__ uint32_t smem_u32(const void* p) {
    return (uint32_t)__cvta_generic_to_shared(p);
}
__device__ __forceinline__ void cpa16(uint32_t dst, const void* src, int sz) {
    asm volatile("cp.async.cg.shared.global [%0], [%1], 16, %2;"
                 :: "r"(dst), "l"(src), "r"(sz) : "memory");
}
__device__ __forceinline__ void cp_commit() {
    asm volatile("cp.async.commit_group;" ::: "memory");
}
template<int N> __device__ __forceinline__ void cp_wait() {
    asm volatile("cp.async.wait_group %0;" :: "n"(N) : "memory");
}
__device__ __forceinline__ void ldsm4(uint32_t* r, uint32_t addr) {
    asm volatile("ldmatrix.sync.aligned.m8n8.x4.shared.b16 {%0,%1,%2,%3}, [%4];"
                 : "=r"(r[0]), "=r"(r[1]), "=r"(r[2]), "=r"(r[3]) : "r"(addr));
}
__device__ __forceinline__ void ldsm4t(uint32_t* r, uint32_t addr) {
    asm volatile("ldmatrix.sync.aligned.m8n8.x4.trans.shared.b16 {%0,%1,%2,%3}, [%4];"
                 : "=r"(r[0]), "=r"(r[1]), "=r"(r[2]), "=r"(r[3]) : "r"(addr));
}
__device__ __forceinline__ void mma_f16(float* c, const uint32_t* a, uint32_t b0, uint32_t b1) {
    asm volatile(
        "mma.sync.aligned.m16n8k16.row.col.f32.f16.f16.f32 "
        "{%0,%1,%2,%3}, {%4,%5,%6,%7}, {%8,%9}, {%0,%1,%2,%3};"
        : "+f"(c[0]), "+f"(c[1]), "+f"(c[2]), "+f"(c[3])
        : "r"(a[0]), "r"(a[1]), "r"(a[2]), "r"(a[3]), "r"(b0), "r"(b1));
}
__device__ __forceinline__ uint32_t packhf(float a, float b) {
    __half2 t = __halves2half2(__float2half_rn(a), __float2half_rn(b));
    return *(uint32_t*)&t;
}

struct GemmSet { const __half* bh; const float* bias; float* out; };

// ---------------- mma.sync fp16 2-term GEMM, BK=64 double-buffered ----------------
// Smem tile: [128 rows][72 halfs] (144B pitch -> conflict-free ldmatrix).
#define GTILE   18432                 // 128*144
#define GSTAGE  (3 * GTILE)           // AH, AL, BH
#define GEMM_SMEM (2 * GSTAGE)        // 110592

__global__ __launch_bounds__(256) void gemm_mma(
    const __half* __restrict__ Ahi, const __half* __restrict__ Alo,
    GemmSet s0, GemmSet s1, GemmSet s2, int M, int K)
{
    extern __shared__ char smem[];
    const uint32_t sb = smem_u32(smem);
    const int tid = threadIdx.x, warp = tid >> 5, lane = tid & 31;
    const GemmSet S = (blockIdx.z == 0) ? s0 : ((blockIdx.z == 1) ? s1 : s2);
    const int nb = blockIdx.x, mb = blockIdx.y;
    const int wm = warp & 3, wn = warp >> 2;

    const __half* gAh = Ahi  + (size_t)mb * 128 * K;
    const __half* gAl = Alo  + (size_t)mb * 128 * K;
    const __half* gBh = S.bh + (size_t)nb * 128 * K;
    const int rows_a = min(128, M - mb * 128);

    auto issue = [&](int kc, int st) {
        uint32_t base = sb + st * GSTAGE;
#pragma unroll
        for (int p = 0; p < 4; p++) {
            int idx = tid + p * 256;       // 0..1023
            int row = idx >> 3, ch = idx & 7;
            bool v = row < rows_a;
            int sz = v ? 16 : 0;
            size_t go = (size_t)row * K + (size_t)kc * 64 + ch * 8;
            uint32_t d = base + (uint32_t)(row * 144 + ch * 16);
            cpa16(d,             v ? (gAh + go) : gAh, sz);
            cpa16(d + GTILE,     v ? (gAl + go) : gAl, sz);
            cpa16(d + 2 * GTILE, gBh + go, 16);
        }
        cp_commit();
    };

    float c[2][8][4];
#pragma unroll
    for (int i = 0; i < 2; i++)
#pragma unroll
        for (int j = 0; j < 8; j++)
#pragma unroll
            for (int e = 0; e < 4; e++) c[i][j][e] = 0.f;

    const int nch = K / 64;
    issue(0, 0);

    const int a_r  = wm * 32 + (lane & 15);
    const int a_c8 = (lane >> 4) * 8;
    const int b_n  = wn * 64 + (lane >> 4) * 8 + (lane & 7);
    const int b_c8 = ((lane >> 3) & 1) * 8;

    for (int kc = 0; kc < nch; kc++) {
        const int st = kc & 1;
        if (kc + 1 < nch) { issue(kc + 1, st ^ 1); cp_wait<1>(); }
        else              { cp_wait<0>(); }
        __syncthreads();

        const uint32_t sa = sb + st * GSTAGE;
#pragma unroll
        for (int ks = 0; ks < 4; ks++) {
            uint32_t ah[2][4], al[2][4];
#pragma unroll
            for (int mf = 0; mf < 2; mf++) {
                uint32_t ad = sa + (uint32_t)((a_r + mf * 16) * 144 + (ks * 16 + a_c8) * 2);
                ldsm4(ah[mf], ad);
                ldsm4(al[mf], ad + GTILE);
            }
            uint32_t bh[8][2];
#pragma unroll
            for (int nf = 0; nf < 4; nf++) {
                uint32_t bd = sa + 2 * GTILE +
                              (uint32_t)((b_n + nf * 16) * 144 + (ks * 16 + b_c8) * 2);
                uint32_t t0[4];
                ldsm4(t0, bd);
                bh[nf * 2][0] = t0[0]; bh[nf * 2][1] = t0[1];
                bh[nf * 2 + 1][0] = t0[2]; bh[nf * 2 + 1][1] = t0[3];
            }
#pragma unroll
            for (int mf = 0; mf < 2; mf++)
#pragma unroll
                for (int nf = 0; nf < 8; nf++) {
                    mma_f16(c[mf][nf], ah[mf], bh[nf][0], bh[nf][1]);
                    mma_f16(c[mf][nf], al[mf], bh[nf][0], bh[nf][1]);
                }
        }
        __syncthreads();
    }

#pragma unroll
    for (int mf = 0; mf < 2; mf++) {
#pragma unroll
        for (int nf = 0; nf < 8; nf++) {
            int row0 = mb * 128 + wm * 32 + mf * 16 + (lane >> 2);
            int col  = nb * 128 + wn * 64 + nf * 8 + (lane & 3) * 2;
            float b0 = S.bias[col], b1 = S.bias[col + 1];
            if (row0 < M) {
                float2 o0 = make_float2(c[mf][nf][0] + b0, c[mf][nf][1] + b1);
                *(float2*)(S.out + (size_t)row0 * HID + col) = o0;
            }
            int row1 = row0 + 8;
            if (row1 < M) {
                float2 o1 = make_float2(c[mf][nf][2] + b0, c[mf][nf][3] + b1);
                *(float2*)(S.out + (size_t)row1 * HID + col) = o1;
            }
        }
    }
}

// ---------------- flash attention, fp16 2-term ----------------
// Q hi/lo in smem; K,V single fp16 streamed (64 keys/stage, double buffered).
#define APITCH 272
#define AQ_H   0
#define AQ_L   34816
#define AST0   69632
#define AKV_V  17408                    // V offset within stage
#define ASTAGE 34816                    // K + V
#define ATTN_SMEM (AST0 + 2 * ASTAGE)   // 139264

__global__ __launch_bounds__(256) void attn_mma(
    const __half* __restrict__ Qh, const __half* __restrict__ Ql,
    const __half* __restrict__ Kh, const __half* __restrict__ Vh,
    float* __restrict__ ctx)
{
    extern __shared__ char smem[];
    const uint32_t sb = smem_u32(smem);
    const int tid = threadIdx.x, w = tid >> 5, lane = tid & 31;
    const int mb = blockIdx.x, h = blockIdx.y;
    const size_t hbase = (size_t)h * S_TOT * HD;

    // load Q tile (128 x 128 halfs, hi & lo)
#pragma unroll
    for (int i = 0; i < 8; i++) {
        int c = tid + i * 256;
        int row = c >> 4, ch = c & 15;
        size_t g = hbase + (size_t)(mb * 128 + row) * HD + ch * 8;
        *(uint4*)(smem + AQ_H + row * APITCH + ch * 16) = *(const uint4*)(Qh + g);
        *(uint4*)(smem + AQ_L + row * APITCH + ch * 16) = *(const uint4*)(Ql + g);
    }

    auto issueKV = [&](int t, int st) {
        uint32_t base = sb + AST0 + st * ASTAGE;
        int key0 = t * 64;
#pragma unroll
        for (int i = 0; i < 4; i++) {
            int c = tid + i * 256;
            int row = c >> 4, ch = c & 15;
            size_t g = hbase + (size_t)(key0 + row) * HD + ch * 8;
            uint32_t d = base + row * APITCH + ch * 16;
            cpa16(d,         Kh + g, 16);
            cpa16(d + AKV_V, Vh + g, 16);
        }
        cp_commit();
    };

    float co[16][4];
#pragma unroll
    for (int i = 0; i < 16; i++)
#pragma unroll
        for (int e = 0; e < 4; e++) co[i][e] = 0.f;
    float m0 = -1e30f, m1 = -1e30f, l0 = 0.f, l1 = 0.f;

    const uint32_t qa_ro = (uint32_t)((w * 16 + (lane & 15)) * APITCH + ((lane >> 4) * 8) * 2);
    const int b_n  = (lane >> 4) * 8 + (lane & 7);
    const int b_c8 = ((lane >> 3) & 1) * 8;
    const uint32_t vt_ro = (uint32_t)((lane & 15) * APITCH + ((lane >> 4) * 8) * 2);

    issueKV(0, 0);

    const int NT = S_TOT / 64;
    for (int t = 0; t < NT; t++) {
        const int st = t & 1;
        if (t + 1 < NT) { issueKV(t + 1, st ^ 1); cp_wait<1>(); }
        else            { cp_wait<0>(); }
        __syncthreads();

        const uint32_t kbase = sb + AST0 + st * ASTAGE;

        // ---- S = (Qh + Ql) @ K^T ----
        float cs[8][4];
#pragma unroll
        for (int i = 0; i < 8; i++)
#pragma unroll
            for (int e = 0; e < 4; e++) cs[i][e] = 0.f;

#pragma unroll
        for (int kt = 0; kt < 8; kt++) {
            uint32_t ah[4], al[4];
            uint32_t qa = sb + qa_ro + (uint32_t)(kt * 32);
            ldsm4(ah, qa + AQ_H);
            ldsm4(al, qa + AQ_L);
#pragma unroll
            for (int nfp = 0; nfp < 4; nfp++) {
                uint32_t bd = kbase + (uint32_t)((b_n + nfp * 16) * APITCH + (kt * 16 + b_c8) * 2);
                uint32_t t0[4];
                ldsm4(t0, bd);
                mma_f16(cs[nfp * 2],     ah, t0[0], t0[1]);
                mma_f16(cs[nfp * 2 + 1], ah, t0[2], t0[3]);
                mma_f16(cs[nfp * 2],     al, t0[0], t0[1]);
                mma_f16(cs[nfp * 2 + 1], al, t0[2], t0[3]);
            }
        }

        // ---- online softmax ----
        float mx0 = m0, mx1 = m1;
#pragma unroll
        for (int nf = 0; nf < 8; nf++) {
            mx0 = fmaxf(mx0, fmaxf(cs[nf][0], cs[nf][1]));
            mx1 = fmaxf(mx1, fmaxf(cs[nf][2], cs[nf][3]));
        }
        mx0 = fmaxf(mx0, __shfl_xor_sync(0xffffffffu, mx0, 1));
        mx0 = fmaxf(mx0, __shfl_xor_sync(0xffffffffu, mx0, 2));
        mx1 = fmaxf(mx1, __shfl_xor_sync(0xffffffffu, mx1, 1));
        mx1 = fmaxf(mx1, __shfl_xor_sync(0xffffffffu, mx1, 2));
        float corr0 = __expf(m0 - mx0), corr1 = __expf(m1 - mx1);
        m0 = mx0; m1 = mx1;

        float rs0 = 0.f, rs1 = 0.f;
        uint32_t ph[4][4], pl[4][4];
#pragma unroll
        for (int kt = 0; kt < 4; kt++) {
#pragma unroll
            for (int hh = 0; hh < 2; hh++) {
                int nf = 2 * kt + hh;
                float p0 = __expf(cs[nf][0] - m0), p1 = __expf(cs[nf][1] - m0);
                float p2 = __expf(cs[nf][2] - m1), p3 = __expf(cs[nf][3] - m1);
                rs0 += p0 + p1; rs1 += p2 + p3;
                float h0 = __half2float(__float2half_rn(p0));
                float h1 = __half2float(__float2half_rn(p1));
                float h2 = __half2float(__float2half_rn(p2));
                float h3 = __half2float(__float2half_rn(p3));
                ph[kt][hh * 2]     = packhf(h0, h1);
                ph[kt][hh * 2 + 1] = packhf(h2, h3);
                pl[kt][hh * 2]     = packhf(p0 - h0, p1 - h1);
                pl[kt][hh * 2 + 1] = packhf(p2 - h2, p3 - h3);
            }
        }
        rs0 += __shfl_xor_sync(0xffffffffu, rs0, 1);
        rs0 += __shfl_xor_sync(0xffffffffu, rs0, 2);
        rs1 += __shfl_xor_sync(0xffffffffu, rs1, 1);
        rs1 += __shfl_xor_sync(0xffffffffu, rs1, 2);
        l0 = l0 * corr0 + rs0;
        l1 = l1 * corr1 + rs1;

#pragma unroll
        for (int nf = 0; nf < 16; nf++) {
            co[nf][0] *= corr0; co[nf][1] *= corr0;
            co[nf][2] *= corr1; co[nf][3] *= corr1;
        }

        // ---- O += (Ph + Pl) @ V ----
        const uint32_t vbase = kbase + AKV_V;
#pragma unroll
        for (int kt = 0; kt < 4; kt++) {
#pragma unroll
            for (int np = 0; np < 8; np++) {
                uint32_t vd = vbase + vt_ro + (uint32_t)(kt * 16 * APITCH + np * 32);
                uint32_t th[4];
                ldsm4t(th, vd);
                mma_f16(co[np * 2],     ph[kt], th[0], th[1]);
                mma_f16(co[np * 2 + 1], ph[kt], th[2], th[3]);
                mma_f16(co[np * 2],     pl[kt], th[0], th[1]);
                mma_f16(co[np * 2 + 1], pl[kt], th[2], th[3]);
            }
        }
        __syncthreads();
    }

    float i0 = 1.f / l0, i1 = 1.f / l1;
    int r0g = mb * 128 + w * 16 + (lane >> 2);
#pragma unroll
    for (int nf = 0; nf < 16; nf++) {
        int col = h * HD + nf * 8 + (lane & 3) * 2;
        *(float2*)(ctx + (size_t)r0g * HID + col) =
            make_float2(co[nf][0] * i0, co[nf][1] * i0);
        *(float2*)(ctx + (size_t)(r0g + 8) * HID + col) =
            make_float2(co[nf][2] * i1, co[nf][3] * i1);
    }
}

// ---------------- fp32 -> fp16 hi/lo split (elementwise) ----------------
__global__ __launch_bounds__(256) void conv_act(
    const float* __restrict__ x, __half* __restrict__ h,
    __half* __restrict__ l, int n4)
{
    int i = blockIdx.x * 256 + threadIdx.x;
    if (i >= n4) return;
    float4 v = ((const float4*)x)[i];
    __half h0 = __float2half_rn(v.x), h1 = __float2half_rn(v.y);
    __half h2 = __float2half_rn(v.z), h3 = __float2half_rn(v.w);
    __half l0 = __float2half_rn(v.x - __half2float(h0));
    __half l1 = __float2half_rn(v.y - __half2float(h1));
    __half l2 = __float2half_rn(v.z - __half2float(h2));
    __half l3 = __float2half_rn(v.w - __half2float(h3));
    ((__half2*)h)[2 * i]     = __half2(h0, h1);
    ((__half2*)h)[2 * i + 1] = __half2(h2, h3);
    ((__half2*)l)[2 * i]     = __half2(l0, l1);
    ((__half2*)l)[2 * i + 1] = __half2(l2, l3);
}

// ---------------- W[K][N] fp32 -> W^T[N][K] fp16 (hi only), batched by z ----------------
struct WTask { const float* W; __half* T; };

__global__ __launch_bounds__(256) void conv_wT(
    WTask t0, WTask t1, WTask t2, int K, int N)
{
    __shared__ float s[32][33];
    const WTask T = (blockIdx.z == 0) ? t0 : ((blockIdx.z == 1) ? t1 : t2);
    const int tx = threadIdx.x & 31, ty = threadIdx.x >> 5;
    const int k0 = blockIdx.y * 32, n0 = blockIdx.x * 32;
#pragma unroll
    for (int r = 0; r < 4; r++)
        s[ty + r * 8][tx] = T.W[(size_t)(k0 + ty + r * 8) * N + n0 + tx];
    __syncthreads();
#pragma unroll
    for (int r = 0; r < 4; r++) {
        int n = n0 + ty + r * 8, k = k0 + tx;
        T.T[(size_t)n * K + k] = __float2half_rn(s[tx][ty + r * 8]);
    }
}

// ---------------- prepare: rms + rope + head layout -> fp16 (q hi/lo, k/v single) ----------------
__global__ __launch_bounds__(128) void prepare_qkv(
    const float* __restrict__ q,  const float* __restrict__ k,  const float* __restrict__ v,
    const float* __restrict__ eq, const float* __restrict__ ek, const float* __restrict__ ev,
    const float* __restrict__ nq, const float* __restrict__ nk,
    const float* __restrict__ naq,const float* __restrict__ nak,
    const float* __restrict__ cosr, const float* __restrict__ sinr,
    __half* __restrict__ qh, __half* __restrict__ ql,
    __half* __restrict__ kh, __half* __restrict__ vh)
{
    const int s = blockIdx.x;
    const int h = blockIdx.y;
    const int d = threadIdx.x;
    const int col = h * HD + d;

    const float *sq, *sk, *sv, *wq, *wk;
    if (s < S_TXT) {
        sq = eq + (size_t)s * HID; sk = ek + (size_t)s * HID; sv = ev + (size_t)s * HID;
        wq = naq; wk = nak;
    } else {
        int si = s - S_TXT;
        sq = q + (size_t)si * HID; sk = k + (size_t)si * HID; sv = v + (size_t)si * HID;
        wq = nq; wk = nk;
    }
    float xq = sq[col], xk = sk[col], xv = sv[col];

    __shared__ float red[8];
    float s2q = xq * xq, s2k = xk * xk;
#pragma unroll
    for (int o = 16; o; o >>= 1) {
        s2q += __shfl_xor_sync(0xffffffffu, s2q, o);
        s2k += __shfl_xor_sync(0xffffffffu, s2k, o);
    }
    int wid = d >> 5, lid = d & 31;
    if (lid == 0) { red[wid] = s2q; red[4 + wid] = s2k; }
    __syncthreads();
    float tq = red[0] + red[1] + red[2] + red[3];
    float tk = red[4] + red[5] + red[6] + red[7];
    float rq = rsqrtf(tq / (float)HD + EPS_F);
    float rk = rsqrtf(tk / (float)HD + EPS_F);
    float nxq = xq * rq * wq[d];
    float nxk = xk * rk * wk[d];

    __shared__ float shq[128], shk[128];
    shq[d] = nxq; shk[d] = nxk;
    __syncthreads();

    float c  = cosr[(size_t)s * HD + d];
    float sn = sinr[(size_t)s * HD + d];
    float oq, ok;
    if ((d & 1) == 0) {
        oq = nxq * c - shq[d + 1] * sn;
        ok = nxk * c - shk[d + 1] * sn;
    } else {
        oq = nxq * c + shq[d - 1] * sn;
        ok = nxk * c + shk[d - 1] * sn;
    }
    oq *= SM_SCALE;

    size_t o = ((size_t)h * S_TOT + s) * HD + d;
    __half hq = __float2half_rn(oq);
    qh[o] = hq;
    ql[o] = __float2half_rn(oq - __half2float(hq));
    kh[o] = __float2half_rn(ok);
    vh[o] = __float2half_rn(xv);
}

// ---------------- IP attention (unchanged, validated) ----------------
__global__ __launch_bounds__(256) void ip_attn(
    const float* __restrict__ q, const float* __restrict__ ipk, const float* __restrict__ ipv,
    const float* __restrict__ wqn, const float* __restrict__ wkn,
    float* __restrict__ ctx)
{
    __shared__ float sK[LIP * HD];
    __shared__ float sV[LIP * HD];
    const int t = threadIdx.x, h = blockIdx.y;
    const int w = t >> 5, lane = t & 31;

#pragma unroll
    for (int i = 0; i < 8; i++) {
        int idx = t + i * 256;
        int r = idx >> 7, c = idx & 127;
        sK[idx] = ipk[(size_t)r * HID + h * HD + c];
        sV[idx] = ipv[(size_t)r * HID + h * HD + c];
    }
    __syncthreads();

    float4 wk4 = *(const float4*)(wkn + lane * 4);
    for (int rr = w; rr < LIP; rr += 8) {
        float4 kv = ((float4*)sK)[rr * 32 + lane];
        float ss = kv.x * kv.x + kv.y * kv.y + kv.z * kv.z + kv.w * kv.w;
#pragma unroll
        for (int o = 16; o; o >>= 1) ss += __shfl_xor_sync(0xffffffffu, ss, o);
        float r = rsqrtf(ss / (float)HD + EPS_F);
        kv.x *= r * wk4.x; kv.y *= r * wk4.y; kv.z *= r * wk4.z; kv.w *= r * wk4.w;
        ((float4*)sK)[rr * 32 + lane] = kv;
    }
    __syncthreads();

    const int s = blockIdx.x * 8 + w;
    float4 q4 = *(const float4*)(q + (size_t)s * HID + h * HD + lane * 4);
    float ss = q4.x * q4.x + q4.y * q4.y + q4.z * q4.z + q4.w * q4.w;
#pragma unroll
    for (int o = 16; o; o >>= 1) ss += __shfl_xor_sync(0xffffffffu, ss, o);
    float rq = rsqrtf(ss / (float)HD + EPS_F);
    float4 wq4 = *(const float4*)(wqn + lane * 4);
    q4.x *= rq * wq4.x; q4.y *= rq * wq4.y; q4.z *= rq * wq4.z; q4.w *= rq * wq4.w;

    float sc[LIP];
#pragma unroll
    for (int j = 0; j < LIP; j++) {
        float4 kv = ((const float4*)sK)[j * 32 + lane];
        float d = q4.x * kv.x + q4.y * kv.y + q4.z * kv.z + q4.w * kv.w;
#pragma unroll
        for (int o = 16; o; o >>= 1) d += __shfl_xor_sync(0xffffffffu, d, o);
        sc[j] = d * SM_SCALE;
    }
    float mx = sc[0];
#pragma unroll
    for (int j = 1; j < LIP; j++) mx = fmaxf(mx, sc[j]);
    float l = 0.f;
#pragma unroll
    for (int j = 0; j < LIP; j++) { sc[j] = __expf(sc[j] - mx); l += sc[j]; }
    float inv = 1.f / l;

    float4 acc = make_float4(0.f, 0.f, 0.f, 0.f);
#pragma unroll
    for (int j = 0; j < LIP; j++) {
        float p = sc[j] * inv;
        float4 vv = ((const float4*)sV)[j * 32 + lane];
        acc.x += p * vv.x; acc.y += p * vv.y; acc.z += p * vv.z; acc.w += p * vv.w;
    }
    float* o = ctx + (size_t)(S_TXT + s) * HID + h * HD + lane * 4;
    float4 cur = *(float4*)o;
    cur.x += acc.x; cur.y += acc.y; cur.z += acc.z; cur.w += acc.w;
    *(float4*)o = cur;
}

// ---------------- host launch ----------------
static float* symf(const void* s) { void* p = nullptr; cudaGetSymbolAddress(&p, s); return (float*)p; }
static __half* symh(const void* s) { void* p = nullptr; cudaGetSymbolAddress(&p, s); return (__half*)p; }

extern "C" void kernel_launch(void* const* d_in, const int* in_sizes, int n_in,
                              void* d_out, int out_size)
{
    const float* hs    = (const float*)d_in[0];
    const float* enc   = (const float*)d_in[1];
    const float* iph   = (const float*)d_in[2];
    const float* rcos  = (const float*)d_in[3];
    const float* rsin  = (const float*)d_in[4];
    const float* Wq    = (const float*)d_in[5];
    const float* bq    = (const float*)d_in[6];
    const float* Wk    = (const float*)d_in[7];
    const float* bk    = (const float*)d_in[8];
    const float* Wv    = (const float*)d_in[9];
    const float* bv    = (const float*)d_in[10];
    const float* nqw   = (const float*)d_in[11];
    const float* nkw   = (const float*)d_in[12];
    const float* Waq   = (const float*)d_in[13];
    const float* baq   = (const float*)d_in[14];
    const float* Wak   = (const float*)d_in[15];
    const float* bak   = (const float*)d_in[16];
    const float* Wav   = (const float*)d_in[17];
    const float* bav   = (const float*)d_in[18];
    const float* naqw  = (const float*)d_in[19];
    const float* nakw  = (const float*)d_in[20];
    const float* Wo    = (const float*)d_in[21];
    const float* bo    = (const float*)d_in[22];
    const float* Wadd  = (const float*)d_in[23];
    const float* badd  = (const float*)d_in[24];
    const float* Wkip  = (const float*)d_in[25];
    const float* bkip  = (const float*)d_in[26];
    const float* Wvip  = (const float*)d_in[27];
    const float* bvip  = (const float*)d_in[28];
    const float* nipq  = (const float*)d_in[29];
    const float* nipk  = (const float*)d_in[30];

    float* out = (float*)d_out;

    float* pq   = symf(g_q);   float* pk   = symf(g_k);   float* pv   = symf(g_v);
    float* peq  = symf(g_eq);  float* pek  = symf(g_ek);  float* pev  = symf(g_ev);
    float* pipk = symf(g_ipk); float* pipv = symf(g_ipv);
    float* pctx = symf(g_ctx);

    __half *aqh = symh(g_aqh), *aql = symh(g_aql);
    __half *akh = symh(g_akh), *avh = symh(g_avh);

    __half *hsh = symh(g_hs_h),  *hsl = symh(g_hs_l);
    __half *ech = symh(g_enc_h), *ecl = symh(g_enc_l);
    __half *iph_h = symh(g_iph_h), *iph_l = symh(g_iph_l);
    __half *cxh = symh(g_ctxh),  *cxl = symh(g_ctxl);
    __half *wqT = symh(g_WqT),  *wkT = symh(g_WkT),  *wvT = symh(g_WvT);
    __half *waqT = symh(g_WaqT), *wakT = symh(g_WakT), *wavT = symh(g_WavT);
    __half *woT = symh(g_WoT),  *wadT = symh(g_WadT);
    __half *wkiT = symh(g_WkiT), *wviT = symh(g_WviT);

    cudaFuncSetAttribute(gemm_mma, cudaFuncAttributeMaxDynamicSharedMemorySize, GEMM_SMEM);
    cudaFuncSetAttribute(attn_mma, cudaFuncAttributeMaxDynamicSharedMemorySize, ATTN_SMEM);

    dim3 wg(HID / 32, HID / 32, 3);
    dim3 wg2(HID / 32, HID / 32, 2);
    dim3 wgip(HID / 32, IPD / 32, 2);

    conv_act<<<(S_IMG * HID / 4 + 255) / 256, 256>>>(hs,  hsh, hsl, S_IMG * HID / 4);
    conv_wT<<<wg, 256>>>(WTask{Wq, wqT}, WTask{Wk, wkT}, WTask{Wv, wvT}, HID, HID);
    conv_act<<<(S_TXT * HID / 4 + 255) / 256, 256>>>(enc, ech, ecl, S_TXT * HID / 4);
    conv_wT<<<wg, 256>>>(WTask{Waq, waqT}, WTask{Wak, wakT}, WTask{Wav, wavT}, HID, HID);
    conv_act<<<(LIP * IPD / 4 + 255) / 256, 256>>>(iph, iph_h, iph_l, LIP * IPD / 4);

    GemmSet sq{wqT, bq, pq}, sk{wkT, bk, pk}, sv{wvT, bv, pv};
    gemm_mma<<<dim3(HID / 128, S_IMG / 128, 3), 256, GEMM_SMEM>>>(hsh, hsl, sq, sk, sv, S_IMG, HID);

    conv_wT<<<wgip, 256>>>(WTask{Wkip, wkiT}, WTask{Wvip, wviT}, WTask{Wkip, wkiT}, IPD, HID);
    GemmSet se1{waqT, baq, peq}, se2{wakT, bak, pek}, se3{wavT, bav, pev};
    gemm_mma<<<dim3(HID / 128, S_TXT / 128, 3), 256, GEMM_SMEM>>>(ech, ecl, se1, se2, se3, S_TXT, HID);
    GemmSet si1{wkiT, bkip, pipk}, si2{wviT, bvip, pipv};
    gemm_mma<<<dim3(HID / 128, 1, 2), 256, GEMM_SMEM>>>(iph_h, iph_l, si1, si2, si1, LIP, IPD);
    conv_wT<<<wg2, 256>>>(WTask{Wo, woT}, WTask{Wadd, wadT}, WTask{Wo, woT}, HID, HID);

    prepare_qkv<<<dim3(S_TOT, NH), 128>>>(pq, pk, pv, peq, pek, pev,
                                          nqw, nkw, naqw, nakw, rcos, rsin,
                                          aqh, aql, akh, avh);

    attn_mma<<<dim3(S_TOT / 128, NH), 256, ATTN_SMEM>>>(aqh, aql, akh, avh, pctx);
    ip_attn<<<dim3(S_IMG / 8, NH), 256>>>(pq, pipk, pipv, nipq, nipk, pctx);

    conv_act<<<(S_TOT * HID / 4 + 255) / 256, 256>>>(pctx, cxh, cxl, S_TOT * HID / 4);

    GemmSet so{woT, bo, out};
    gemm_mma<<<dim3(HID / 128, S_IMG / 128, 1), 256, GEMM_SMEM>>>(
        cxh + (size_t)S_TXT * HID, cxl + (size_t)S_TXT * HID, so, so, so, S_IMG, HID);

    GemmSet sa{wadT, badd, out + (size_t)S_IMG * HID};
    gemm_mma<<<dim3(HID / 128, S_TXT / 128, 1), 256, GEMM_SMEM>>>(
        cxh, cxl, sa, sa, sa, S_TXT, HID);
}